// round 1
// baseline (speedup 1.0000x reference)
#include <cuda_runtime.h>
#include <math.h>

#define T_TOK 2048
#define HDIM  1024
#define NE    16
#define TOPK  4
#define NG    4
#define TGSEL 2
#define IMOE  512
#define ISH   1024
#define RSCALE 2.5f

#define TM 64
#define TN 64
#define TK 16
#define SPAD 4   // smem pad: row stride 68 floats = 272B (16B aligned)

// ---------------- device scratch (module-level, no runtime alloc) -------------
__device__ int   g_tidx[T_TOK * TOPK];
__device__ float g_tw  [T_TOK * TOPK];
__device__ int   g_cnt [NE];
__device__ int   g_cur [NE];
__device__ int   g_off [NE + 1];
__device__ int   g_ptok[T_TOK * TOPK];
__device__ float g_pw  [T_TOK * TOPK];
__device__ float g_hbuf[(size_t)T_TOK * TOPK * IMOE];  // 16 MB
__device__ float g_hs  [(size_t)T_TOK * ISH];          // 8 MB

// ---------------- init -------------------------------------------------------
__global__ void init_kernel() {
    int i = threadIdx.x;
    if (i < NE) { g_cnt[i] = 0; g_cur[i] = 0; }
}

// ---------------- router: scores + grouped top-k ------------------------------
__global__ void router_kernel(const float* __restrict__ x,
                              const float* __restrict__ rw,
                              const float* __restrict__ ebias) {
    int t    = blockIdx.x;
    int w    = threadIdx.x >> 5;   // expert index 0..15
    int lane = threadIdx.x & 31;

    const float* xr = x  + (size_t)t * HDIM;
    const float* wr = rw + (size_t)w * HDIM;
    float s = 0.f;
    for (int k = lane; k < HDIM; k += 32) s += xr[k] * wr[k];
    #pragma unroll
    for (int o = 16; o; o >>= 1) s += __shfl_xor_sync(0xffffffffu, s, o);

    __shared__ float sdot[NE];
    if (lane == 0) sdot[w] = s;
    __syncthreads();

    if (threadIdx.x == 0) {
        float sraw[NE], sc[NE];
        #pragma unroll
        for (int e = 0; e < NE; e++) {
            sraw[e] = 1.f / (1.f + expf(-sdot[e]));
            sc[e]   = sraw[e] + ebias[e];
        }
        // group score = sum of top-2 in each group of 4
        float gsc[NG];
        #pragma unroll
        for (int g = 0; g < NG; g++) {
            float m1 = -1e30f, m2 = -1e30f;
            #pragma unroll
            for (int j = 0; j < NE / NG; j++) {
                float v = sc[g * (NE / NG) + j];
                if (v > m1) { m2 = m1; m1 = v; }
                else if (v > m2) { m2 = v; }
            }
            gsc[g] = m1 + m2;
        }
        // top-2 groups (first index wins ties, like jax top_k)
        bool gsel[NG] = {false, false, false, false};
        for (int r = 0; r < TGSEL; r++) {
            int best = -1; float bv = -1e30f;
            for (int g = 0; g < NG; g++)
                if (!gsel[g] && gsc[g] > bv) { bv = gsc[g]; best = g; }
            gsel[best] = true;
        }
        float masked[NE];
        #pragma unroll
        for (int e = 0; e < NE; e++)
            masked[e] = gsel[e / (NE / NG)] ? sc[e] : 0.0f;
        // top-4 experts, gather weights from UNBIASED sigmoid scores
        int   idx[TOPK]; float tw[TOPK]; float wsum = 0.f;
        for (int r = 0; r < TOPK; r++) {
            int best = 0; float bv = -1e30f;
            for (int e = 0; e < NE; e++)
                if (masked[e] > bv) { bv = masked[e]; best = e; }
            idx[r] = best; tw[r] = sraw[best];
            masked[best] = -1e30f;
            wsum += tw[r];
        }
        float inv = RSCALE / (wsum + 1e-20f);
        for (int r = 0; r < TOPK; r++) {
            g_tidx[t * TOPK + r] = idx[r];
            g_tw  [t * TOPK + r] = tw[r] * inv;
            atomicAdd(&g_cnt[idx[r]], 1);
        }
    }
}

// ---------------- scan + scatter ----------------------------------------------
__global__ void scan_kernel() {
    if (threadIdx.x == 0) {
        int acc = 0;
        for (int e = 0; e < NE; e++) { g_off[e] = acc; acc += g_cnt[e]; }
        g_off[NE] = acc;
    }
}

__global__ void scatter_kernel() {
    int s = blockIdx.x * blockDim.x + threadIdx.x;
    if (s >= T_TOK * TOPK) return;
    int e   = g_tidx[s];
    int pos = g_off[e] + atomicAdd(&g_cur[e], 1);
    g_ptok[pos] = s >> 2;   // token id
    g_pw  [pos] = g_tw[s];
}

// ---------------- fused gate+up GEMM (+silu*up) --------------------------------
// C-rows: expert-grouped gathered tokens (ROUTED) or all tokens (shared).
// A[m][k] = x[token(m)][k]; Bg/Bu[n][k] = gate/up weight rows. C = 64x64 per block.
template<bool ROUTED>
__global__ void __launch_bounds__(256)
gateup_kernel(const float* __restrict__ x,
              const float* __restrict__ gw,
              const float* __restrict__ uw,
              int I) {
    int e = ROUTED ? blockIdx.z : 0;
    int rbeg, rend;
    if (ROUTED) { rbeg = g_off[e]; rend = g_off[e + 1]; }
    else        { rbeg = 0;        rend = T_TOK; }
    int row0 = rbeg + blockIdx.y * TM;
    if (row0 >= rend) return;
    int n0 = blockIdx.x * TN;

    const float* gwe = gw + (size_t)e * I * HDIM;
    const float* uwe = uw + (size_t)e * I * HDIM;

    __shared__ __align__(16) float As[TK][TM + SPAD];
    __shared__ __align__(16) float Bg[TK][TN + SPAD];
    __shared__ __align__(16) float Bu[TK][TN + SPAD];

    int tid  = threadIdx.x;
    int tx   = tid & 15, ty = tid >> 4;
    int lrow = tid >> 2;           // 0..63
    int lk   = (tid & 3) * 4;      // 0,4,8,12

    int  arow   = row0 + lrow;
    bool avalid = (arow < rend);
    int  atok   = 0;
    if (avalid) atok = ROUTED ? g_ptok[arow] : arow;
    const float* aptr = x   + (size_t)atok * HDIM + lk;
    const float* gptr = gwe + (size_t)(n0 + lrow) * HDIM + lk;
    const float* uptr = uwe + (size_t)(n0 + lrow) * HDIM + lk;

    float accg[4][4], accu[4][4];
    #pragma unroll
    for (int i = 0; i < 4; i++)
        #pragma unroll
        for (int j = 0; j < 4; j++) { accg[i][j] = 0.f; accu[i][j] = 0.f; }

    for (int k0 = 0; k0 < HDIM; k0 += TK) {
        float4 a4 = make_float4(0.f, 0.f, 0.f, 0.f);
        if (avalid) a4 = *(const float4*)(aptr + k0);
        float4 g4 = *(const float4*)(gptr + k0);
        float4 u4 = *(const float4*)(uptr + k0);
        __syncthreads();
        As[lk + 0][lrow] = a4.x; As[lk + 1][lrow] = a4.y;
        As[lk + 2][lrow] = a4.z; As[lk + 3][lrow] = a4.w;
        Bg[lk + 0][lrow] = g4.x; Bg[lk + 1][lrow] = g4.y;
        Bg[lk + 2][lrow] = g4.z; Bg[lk + 3][lrow] = g4.w;
        Bu[lk + 0][lrow] = u4.x; Bu[lk + 1][lrow] = u4.y;
        Bu[lk + 2][lrow] = u4.z; Bu[lk + 3][lrow] = u4.w;
        __syncthreads();
        #pragma unroll
        for (int k = 0; k < TK; k++) {
            float4 av = *(const float4*)&As[k][ty * 4];
            float4 gv = *(const float4*)&Bg[k][tx * 4];
            float4 uv = *(const float4*)&Bu[k][tx * 4];
            float aa[4] = {av.x, av.y, av.z, av.w};
            float gg[4] = {gv.x, gv.y, gv.z, gv.w};
            float uu[4] = {uv.x, uv.y, uv.z, uv.w};
            #pragma unroll
            for (int i = 0; i < 4; i++)
                #pragma unroll
                for (int j = 0; j < 4; j++) {
                    accg[i][j] = fmaf(aa[i], gg[j], accg[i][j]);
                    accu[i][j] = fmaf(aa[i], uu[j], accu[i][j]);
                }
        }
    }

    float* hout = ROUTED ? g_hbuf : g_hs;
    #pragma unroll
    for (int i = 0; i < 4; i++) {
        int r = row0 + ty * 4 + i;
        if (r < rend) {
            float* po = hout + (size_t)r * I + n0 + tx * 4;
            float4 hv;
            float g, u;
            g = accg[i][0]; u = accu[i][0]; hv.x = g * u / (1.f + expf(-g));
            g = accg[i][1]; u = accu[i][1]; hv.y = g * u / (1.f + expf(-g));
            g = accg[i][2]; u = accu[i][2]; hv.z = g * u / (1.f + expf(-g));
            g = accg[i][3]; u = accu[i][3]; hv.w = g * u / (1.f + expf(-g));
            *(float4*)po = hv;
        }
    }
}

// ---------------- down GEMM ----------------------------------------------------
// ROUTED: out[tok] += w * (h @ dw^T) via atomics. shared: out[tok] = h @ dw^T (store).
template<bool ROUTED>
__global__ void __launch_bounds__(256)
down_kernel(const float* __restrict__ dw,
            float* __restrict__ out, int I) {
    int e = ROUTED ? blockIdx.z : 0;
    int rbeg, rend;
    if (ROUTED) { rbeg = g_off[e]; rend = g_off[e + 1]; }
    else        { rbeg = 0;        rend = T_TOK; }
    int row0 = rbeg + blockIdx.y * TM;
    if (row0 >= rend) return;
    int n0 = blockIdx.x * TN;   // over HDIM

    const float* hin = ROUTED ? g_hbuf : g_hs;
    const float* dwe = dw + (size_t)e * HDIM * I;

    __shared__ __align__(16) float As[TK][TM + SPAD];
    __shared__ __align__(16) float Bs[TK][TN + SPAD];

    int tid  = threadIdx.x;
    int tx   = tid & 15, ty = tid >> 4;
    int lrow = tid >> 2;
    int lk   = (tid & 3) * 4;

    int  arow   = row0 + lrow;
    bool avalid = (arow < rend);
    const float* aptr = hin + (size_t)(avalid ? arow : rbeg) * I + lk;
    const float* bptr = dwe + (size_t)(n0 + lrow) * I + lk;

    float acc[4][4];
    #pragma unroll
    for (int i = 0; i < 4; i++)
        #pragma unroll
        for (int j = 0; j < 4; j++) acc[i][j] = 0.f;

    for (int k0 = 0; k0 < I; k0 += TK) {
        float4 a4 = make_float4(0.f, 0.f, 0.f, 0.f);
        if (avalid) a4 = *(const float4*)(aptr + k0);
        float4 b4 = *(const float4*)(bptr + k0);
        __syncthreads();
        As[lk + 0][lrow] = a4.x; As[lk + 1][lrow] = a4.y;
        As[lk + 2][lrow] = a4.z; As[lk + 3][lrow] = a4.w;
        Bs[lk + 0][lrow] = b4.x; Bs[lk + 1][lrow] = b4.y;
        Bs[lk + 2][lrow] = b4.z; Bs[lk + 3][lrow] = b4.w;
        __syncthreads();
        #pragma unroll
        for (int k = 0; k < TK; k++) {
            float4 av = *(const float4*)&As[k][ty * 4];
            float4 bv = *(const float4*)&Bs[k][tx * 4];
            float aa[4] = {av.x, av.y, av.z, av.w};
            float bb[4] = {bv.x, bv.y, bv.z, bv.w};
            #pragma unroll
            for (int i = 0; i < 4; i++)
                #pragma unroll
                for (int j = 0; j < 4; j++)
                    acc[i][j] = fmaf(aa[i], bb[j], acc[i][j]);
        }
    }

    #pragma unroll
    for (int i = 0; i < 4; i++) {
        int r = row0 + ty * 4 + i;
        if (r < rend) {
            if (ROUTED) {
                int   tok = g_ptok[r];
                float w   = g_pw[r];
                float* po = out + (size_t)tok * HDIM + n0 + tx * 4;
                atomicAdd(po + 0, acc[i][0] * w);
                atomicAdd(po + 1, acc[i][1] * w);
                atomicAdd(po + 2, acc[i][2] * w);
                atomicAdd(po + 3, acc[i][3] * w);
            } else {
                float* po = out + (size_t)r * HDIM + n0 + tx * 4;
                float4 v = make_float4(acc[i][0], acc[i][1], acc[i][2], acc[i][3]);
                *(float4*)po = v;
            }
        }
    }
}

// ---------------- launch --------------------------------------------------------
extern "C" void kernel_launch(void* const* d_in, const int* in_sizes, int n_in,
                              void* d_out, int out_size) {
    const float* x   = (const float*)d_in[0];  // [1,2048,1024]
    const float* rw  = (const float*)d_in[1];  // [16,1024]
    const float* eb  = (const float*)d_in[2];  // [16]
    const float* gw  = (const float*)d_in[3];  // [16,512,1024]
    const float* uw  = (const float*)d_in[4];  // [16,512,1024]
    const float* dw  = (const float*)d_in[5];  // [16,1024,512]
    const float* shg = (const float*)d_in[6];  // [1024,1024]
    const float* shu = (const float*)d_in[7];  // [1024,1024]
    const float* shd = (const float*)d_in[8];  // [1024,1024]
    float* out = (float*)d_out;

    init_kernel<<<1, 32>>>();
    router_kernel<<<T_TOK, NE * 32>>>(x, rw, eb);
    scan_kernel<<<1, 32>>>();
    scatter_kernel<<<(T_TOK * TOPK + 255) / 256, 256>>>();

    // shared expert (its down-proj STORES, initializing out)
    gateup_kernel<false><<<dim3(ISH / TN, T_TOK / TM, 1), 256>>>(x, shg, shu, ISH);
    down_kernel<false><<<dim3(HDIM / TN, T_TOK / TM, 1), 256>>>(shd, out, ISH);

    // routed experts (atomicAdd on top)
    gateup_kernel<true><<<dim3(IMOE / TN, T_TOK / TM, NE), 256>>>(x, gw, uw, IMOE);
    down_kernel<true><<<dim3(HDIM / TN, T_TOK / TM, NE), 256>>>(dw, out, IMOE);
}

// round 3
// speedup vs baseline: 2.1376x; 2.1376x over previous
#include <cuda_runtime.h>
#include <cuda_bf16.h>
#include <math.h>
#include <stdint.h>

#define T_TOK 2048
#define HDIM  1024
#define NE    16
#define TOPK  4
#define NG    4
#define TGSEL 2
#define IMOE  512
#define RSCALE 2.5f

// ======================= device scratch (static, no runtime alloc) ============
__device__ int   g_tidx[T_TOK * TOPK];
__device__ float g_tw  [T_TOK * TOPK];
__device__ int   g_cnt [NE];
__device__ int   g_cur [NE];
__device__ int   g_off [NE + 1];
__device__ int   g_ptok[T_TOK * TOPK];
__device__ int   g_pos [T_TOK * TOPK];
__device__ float g_pw  [T_TOK * TOPK];
__device__ float g_gu  [(size_t)T_TOK * TOPK * 1024];  // routed gate|up
__device__ float g_h   [(size_t)T_TOK * TOPK * 512];   // routed silu(g)*u
__device__ float g_y   [(size_t)T_TOK * TOPK * 1024];  // routed down (weighted)
__device__ float g_gu_sh[(size_t)T_TOK * 2048];        // shared gate|up
__device__ float g_hs  [(size_t)T_TOK * 1024];         // shared h
__device__ float g_ysh [(size_t)T_TOK * 1024];         // shared down

// ======================= routing ==============================================
__global__ void init_kernel() {
    int i = threadIdx.x;
    if (i < NE) { g_cnt[i] = 0; g_cur[i] = 0; }
}

__global__ void router_kernel(const float* __restrict__ x,
                              const float* __restrict__ rw,
                              const float* __restrict__ ebias) {
    int t    = blockIdx.x;
    int w    = threadIdx.x >> 5;
    int lane = threadIdx.x & 31;

    const float* xr = x  + (size_t)t * HDIM;
    const float* wr = rw + (size_t)w * HDIM;
    float s = 0.f;
    for (int k = lane; k < HDIM; k += 32) s += xr[k] * wr[k];
    #pragma unroll
    for (int o = 16; o; o >>= 1) s += __shfl_xor_sync(0xffffffffu, s, o);

    __shared__ float sdot[NE];
    if (lane == 0) sdot[w] = s;
    __syncthreads();

    if (threadIdx.x == 0) {
        float sraw[NE], sc[NE];
        #pragma unroll
        for (int e = 0; e < NE; e++) {
            sraw[e] = 1.f / (1.f + expf(-sdot[e]));
            sc[e]   = sraw[e] + ebias[e];
        }
        float gsc[NG];
        #pragma unroll
        for (int g = 0; g < NG; g++) {
            float m1 = -1e30f, m2 = -1e30f;
            #pragma unroll
            for (int j = 0; j < NE / NG; j++) {
                float v = sc[g * (NE / NG) + j];
                if (v > m1) { m2 = m1; m1 = v; }
                else if (v > m2) { m2 = v; }
            }
            gsc[g] = m1 + m2;
        }
        bool gsel[NG] = {false, false, false, false};
        for (int r = 0; r < TGSEL; r++) {
            int best = -1; float bv = -1e30f;
            for (int g = 0; g < NG; g++)
                if (!gsel[g] && gsc[g] > bv) { bv = gsc[g]; best = g; }
            gsel[best] = true;
        }
        float masked[NE];
        #pragma unroll
        for (int e = 0; e < NE; e++)
            masked[e] = gsel[e / (NE / NG)] ? sc[e] : 0.0f;
        int idx[TOPK]; float tw[TOPK]; float wsum = 0.f;
        for (int r = 0; r < TOPK; r++) {
            int best = 0; float bv = -1e30f;
            for (int e = 0; e < NE; e++)
                if (masked[e] > bv) { bv = masked[e]; best = e; }
            idx[r] = best; tw[r] = sraw[best];
            masked[best] = -1e30f;
            wsum += tw[r];
        }
        float inv = RSCALE / (wsum + 1e-20f);
        for (int r = 0; r < TOPK; r++) {
            g_tidx[t * TOPK + r] = idx[r];
            g_tw  [t * TOPK + r] = tw[r] * inv;
            atomicAdd(&g_cnt[idx[r]], 1);
        }
    }
}

__global__ void scan_kernel() {
    if (threadIdx.x == 0) {
        int acc = 0;
        for (int e = 0; e < NE; e++) { g_off[e] = acc; acc += g_cnt[e]; }
        g_off[NE] = acc;
    }
}

__global__ void scatter_kernel() {
    int s = blockIdx.x * blockDim.x + threadIdx.x;
    if (s >= T_TOK * TOPK) return;
    int e   = g_tidx[s];
    int pos = g_off[e] + atomicAdd(&g_cur[e], 1);
    g_ptok[pos] = s >> 2;
    g_pw  [pos] = g_tw[s];
    g_pos [s]   = pos;
}

// ======================= HMMA 3-split bf16 GEMM ================================
// C[128x128] block = A[128xK] @ B[128xK]^T, fp32 in/out, bf16 hi/lo split,
// fp32 accumulation via mma.sync.m16n8k16 (sm_80 PTX — legal on base sm_103).
// smem layout per stage (bytes): Ah@0 Al@10240 Bh@20480 Bl@30720; stage stride 40960.
#define ROWB   80                // bytes per smem row (40 bf16: 32 data + 8 pad)
#define AH_OFF 0
#define AL_OFF 10240
#define BH_OFF 20480
#define BL_OFF 30720
#define STG_B  40960
#define SMEM_DYN (2 * STG_B)

static __device__ __forceinline__ uint32_t smem_u32(const void* p) {
    uint32_t a;
    asm("{ .reg .u64 t; cvta.to.shared.u64 t, %1; cvt.u32.u64 %0, t; }"
        : "=r"(a) : "l"(p));
    return a;
}

#define LDSM_X4(r0, r1, r2, r3, addr) \
    asm volatile("ldmatrix.sync.aligned.m8n8.x4.shared.b16 {%0,%1,%2,%3}, [%4];" \
        : "=r"(r0), "=r"(r1), "=r"(r2), "=r"(r3) : "r"(addr))

#define MMA16816(d, a, b) \
    asm volatile("mma.sync.aligned.m16n8k16.row.col.f32.bf16.bf16.f32 " \
        "{%0,%1,%2,%3},{%4,%5,%6,%7},{%8,%9},{%0,%1,%2,%3};" \
        : "+f"((d)[0]), "+f"((d)[1]), "+f"((d)[2]), "+f"((d)[3]) \
        : "r"((a)[0]), "r"((a)[1]), "r"((a)[2]), "r"((a)[3]), \
          "r"((b)[0]), "r"((b)[1]))

static __device__ __forceinline__ void split_store(uint32_t s_hi, uint32_t s_lo, float4 v) {
    __nv_bfloat162 h0 = __float22bfloat162_rn(make_float2(v.x, v.y));
    __nv_bfloat162 h1 = __float22bfloat162_rn(make_float2(v.z, v.w));
    float2 f0 = __bfloat1622float2(h0);
    float2 f1 = __bfloat1622float2(h1);
    __nv_bfloat162 l0 = __float22bfloat162_rn(make_float2(v.x - f0.x, v.y - f0.y));
    __nv_bfloat162 l1 = __float22bfloat162_rn(make_float2(v.z - f1.x, v.w - f1.y));
    uint32_t uh0 = *(uint32_t*)&h0, uh1 = *(uint32_t*)&h1;
    uint32_t ul0 = *(uint32_t*)&l0, ul1 = *(uint32_t*)&l1;
    asm volatile("st.shared.v2.b32 [%0], {%1,%2};" :: "r"(s_hi), "r"(uh0), "r"(uh1) : "memory");
    asm volatile("st.shared.v2.b32 [%0], {%1,%2};" :: "r"(s_lo), "r"(ul0), "r"(ul1) : "memory");
}

template<bool GROUPED, bool TOKMAP, bool WEIGHT>
__global__ void __launch_bounds__(256)
gemm3_kernel(const float* __restrict__ Asrc, int lda,
             const float* __restrict__ B0, const float* __restrict__ B1,
             size_t b_estride, int nb_half,
             int KD, float* __restrict__ Cout, int ldc)
{
    int e = blockIdx.z;
    int rbeg, rend;
    if (GROUPED) { rbeg = g_off[e]; rend = g_off[e + 1]; }
    else         { rbeg = 0;        rend = T_TOK; }
    int row0 = rbeg + blockIdx.y * 128;
    if (row0 >= rend) return;
    int n0 = blockIdx.x * 128;

    const float* Bsel; int brow0;
    if (n0 < nb_half) { Bsel = B0 + (size_t)e * b_estride; brow0 = n0; }
    else              { Bsel = B1 + (size_t)e * b_estride; brow0 = n0 - nb_half; }

    extern __shared__ __align__(16) char dynsmem[];
    uint32_t sbase = smem_u32(dynsmem);

    int tid  = threadIdx.x;
    int lane = tid & 31, wid = tid >> 5;
    int wm = (wid >> 2) * 64;      // warp m offset (0 / 64)
    int wn = (wid & 3) * 32;       // warp n offset (0..96)

    // ---- staging: thread (r = tid>>1, half = tid&1) handles 16 k-elems -------
    int srow = tid >> 1;
    int kh   = (tid & 1) * 16;
    int  arow_s  = row0 + srow;
    bool avalid  = (arow_s < rend);
    const float* aptr = Asrc;
    if (avalid) {
        int tokr = TOKMAP ? g_ptok[arow_s] : arow_s;
        aptr = Asrc + (size_t)tokr * lda + kh;
    }
    const float* bptr = Bsel + (size_t)(brow0 + srow) * KD + kh;
    uint32_t st_off = (uint32_t)(srow * ROWB + (tid & 1) * 32);

    // ---- ldmatrix per-lane address bases --------------------------------------
    int a_r  = wm + (lane & 7) + ((lane >> 3) & 1) * 8;
    int a_k  = ((lane >> 4) & 1) * 8;
    uint32_t a_lm = (uint32_t)(a_r * ROWB + a_k * 2);
    int b_r  = wn + (lane & 7) + ((lane >> 4) & 1) * 8;
    int b_k  = ((lane >> 3) & 1) * 8;
    uint32_t b_lm = (uint32_t)(b_r * ROWB + b_k * 2);

    float acc[4][4][4];
    #pragma unroll
    for (int i = 0; i < 4; i++)
        #pragma unroll
        for (int j = 0; j < 4; j++)
            #pragma unroll
            for (int q = 0; q < 4; q++) acc[i][j][q] = 0.f;

    int nchunk = KD >> 5;
    float4 pa[4], pb[4];

    // prologue: load + stage chunk 0
    #pragma unroll
    for (int j = 0; j < 4; j++) {
        pa[j] = avalid ? *(const float4*)(aptr + 4 * j) : make_float4(0.f, 0.f, 0.f, 0.f);
        pb[j] = *(const float4*)(bptr + 4 * j);
    }
    #pragma unroll
    for (int j = 0; j < 4; j++) {
        split_store(sbase + AH_OFF + st_off + 8 * j, sbase + AL_OFF + st_off + 8 * j, pa[j]);
        split_store(sbase + BH_OFF + st_off + 8 * j, sbase + BL_OFF + st_off + 8 * j, pb[j]);
    }
    __syncthreads();

    for (int ch = 0; ch < nchunk; ch++) {
        int stage = ch & 1;
        uint32_t sb = sbase + (uint32_t)stage * STG_B;

        // prefetch next chunk into registers
        if (ch + 1 < nchunk) {
            int k0 = (ch + 1) << 5;
            #pragma unroll
            for (int j = 0; j < 4; j++) {
                pa[j] = avalid ? *(const float4*)(aptr + k0 + 4 * j) : make_float4(0.f, 0.f, 0.f, 0.f);
                pb[j] = *(const float4*)(bptr + k0 + 4 * j);
            }
        }

        // MMA over this chunk (2 k16 steps)
        #pragma unroll
        for (int ks = 0; ks < 2; ks++) {
            uint32_t kso = (uint32_t)(ks * 32);
            uint32_t ah[4][4], al[4][4];
            #pragma unroll
            for (int mt = 0; mt < 4; mt++) {
                uint32_t ad = sb + a_lm + (uint32_t)(mt * 16 * ROWB) + kso;
                LDSM_X4(ah[mt][0], ah[mt][1], ah[mt][2], ah[mt][3], ad + AH_OFF);
                LDSM_X4(al[mt][0], al[mt][1], al[mt][2], al[mt][3], ad + AL_OFF);
            }
            uint32_t bh[4][2], bl[4][2];
            #pragma unroll
            for (int nt2 = 0; nt2 < 2; nt2++) {
                uint32_t bd = sb + b_lm + (uint32_t)(nt2 * 16 * ROWB) + kso;
                uint32_t r0, r1, r2, r3;
                LDSM_X4(r0, r1, r2, r3, bd + BH_OFF);
                bh[2 * nt2][0] = r0; bh[2 * nt2][1] = r1;
                bh[2 * nt2 + 1][0] = r2; bh[2 * nt2 + 1][1] = r3;
                LDSM_X4(r0, r1, r2, r3, bd + BL_OFF);
                bl[2 * nt2][0] = r0; bl[2 * nt2][1] = r1;
                bl[2 * nt2 + 1][0] = r2; bl[2 * nt2 + 1][1] = r3;
            }
            #pragma unroll
            for (int mt = 0; mt < 4; mt++)
                #pragma unroll
                for (int nt = 0; nt < 4; nt++) {
                    MMA16816(acc[mt][nt], ah[mt], bh[nt]);
                    MMA16816(acc[mt][nt], al[mt], bh[nt]);
                    MMA16816(acc[mt][nt], ah[mt], bl[nt]);
                }
        }

        if (ch + 1 < nchunk) {
            __syncthreads();   // all warps done reading stage ch-1 (and ch)
            uint32_t so = sbase + (uint32_t)((stage ^ 1)) * STG_B;
            #pragma unroll
            for (int j = 0; j < 4; j++) {
                split_store(so + AH_OFF + st_off + 8 * j, so + AL_OFF + st_off + 8 * j, pa[j]);
                split_store(so + BH_OFF + st_off + 8 * j, so + BL_OFF + st_off + 8 * j, pb[j]);
            }
            __syncthreads();
        }
    }

    // ---- epilogue ----
    int g = lane >> 2, t4 = lane & 3;
    #pragma unroll
    for (int mt = 0; mt < 4; mt++) {
        int R0 = row0 + wm + mt * 16 + g;
        int R1 = R0 + 8;
        bool v0 = (R0 < rend), v1 = (R1 < rend);
        float w0 = 1.f, w1 = 1.f;
        if (WEIGHT) { if (v0) w0 = g_pw[R0]; if (v1) w1 = g_pw[R1]; }
        #pragma unroll
        for (int nt = 0; nt < 4; nt++) {
            int C = n0 + wn + nt * 8 + t4 * 2;
            if (v0) {
                float2 o = make_float2(acc[mt][nt][0] * w0, acc[mt][nt][1] * w0);
                *(float2*)(Cout + (size_t)R0 * ldc + C) = o;
            }
            if (v1) {
                float2 o = make_float2(acc[mt][nt][2] * w1, acc[mt][nt][3] * w1);
                *(float2*)(Cout + (size_t)R1 * ldc + C) = o;
            }
        }
    }
}

// ======================= elementwise kernels ===================================
__global__ void act_kernel(const float* __restrict__ gu, float* __restrict__ h,
                           int ld, int I, int shf) {
    int idx = blockIdx.x * blockDim.x + threadIdx.x;   // float4 units
    int r = idx >> shf;
    int c = (idx - (r << shf)) << 2;
    const float4 g4 = *(const float4*)(gu + (size_t)r * ld + c);
    const float4 u4 = *(const float4*)(gu + (size_t)r * ld + I + c);
    float4 hv;
    hv.x = g4.x * u4.x / (1.f + expf(-g4.x));
    hv.y = g4.y * u4.y / (1.f + expf(-g4.y));
    hv.z = g4.z * u4.z / (1.f + expf(-g4.z));
    hv.w = g4.w * u4.w / (1.f + expf(-g4.w));
    *(float4*)(h + (size_t)r * I + c) = hv;
}

__global__ void combine_kernel(float* __restrict__ out) {
    int idx = blockIdx.x * blockDim.x + threadIdx.x;   // float4 units
    int t = idx >> 8;
    int c = (idx & 255) << 2;
    float4 acc = *(const float4*)(g_ysh + (size_t)t * 1024 + c);
    #pragma unroll
    for (int r = 0; r < TOPK; r++) {
        int p = g_pos[t * TOPK + r];
        const float4 v = *(const float4*)(g_y + (size_t)p * 1024 + c);
        acc.x += v.x; acc.y += v.y; acc.z += v.z; acc.w += v.w;
    }
    *(float4*)(out + (size_t)t * 1024 + c) = acc;
}

// ======================= launch ================================================
extern "C" void kernel_launch(void* const* d_in, const int* in_sizes, int n_in,
                              void* d_out, int out_size) {
    const float* x   = (const float*)d_in[0];
    const float* rw  = (const float*)d_in[1];
    const float* eb  = (const float*)d_in[2];
    const float* gw  = (const float*)d_in[3];
    const float* uw  = (const float*)d_in[4];
    const float* dw  = (const float*)d_in[5];
    const float* shg = (const float*)d_in[6];
    const float* shu = (const float*)d_in[7];
    const float* shd = (const float*)d_in[8];
    float* out = (float*)d_out;

    cudaFuncSetAttribute(gemm3_kernel<false, false, false>,
                         cudaFuncAttributeMaxDynamicSharedMemorySize, SMEM_DYN);
    cudaFuncSetAttribute(gemm3_kernel<true, true, false>,
                         cudaFuncAttributeMaxDynamicSharedMemorySize, SMEM_DYN);
    cudaFuncSetAttribute(gemm3_kernel<true, false, true>,
                         cudaFuncAttributeMaxDynamicSharedMemorySize, SMEM_DYN);

    float* ggu  = nullptr; float* gh = nullptr; float* gy = nullptr;
    float* ggus = nullptr; float* ghs = nullptr; float* gys = nullptr;
    cudaGetSymbolAddress((void**)&ggu,  g_gu);
    cudaGetSymbolAddress((void**)&gh,   g_h);
    cudaGetSymbolAddress((void**)&gy,   g_y);
    cudaGetSymbolAddress((void**)&ggus, g_gu_sh);
    cudaGetSymbolAddress((void**)&ghs,  g_hs);
    cudaGetSymbolAddress((void**)&gys,  g_ysh);

    init_kernel<<<1, 32>>>();
    router_kernel<<<T_TOK, NE * 32>>>(x, rw, eb);
    scan_kernel<<<1, 32>>>();
    scatter_kernel<<<(T_TOK * TOPK + 255) / 256, 256>>>();

    // ---- shared expert: gu = [x@shg^T | x@shu^T] (N=2048), K=1024 ----
    gemm3_kernel<false, false, false><<<dim3(16, 16, 1), 256, SMEM_DYN>>>(
        x, HDIM, shg, shu, 0, 1024, 1024, ggus, 2048);
    act_kernel<<<(T_TOK * 1024 / 4) / 256, 256>>>(ggus, ghs, 2048, 1024, 8);
    gemm3_kernel<false, false, false><<<dim3(8, 16, 1), 256, SMEM_DYN>>>(
        ghs, 1024, shd, shd, 0, 1 << 30, 1024, gys, 1024);

    // ---- routed experts (32 m-blocks per expert covers worst-case skew) ----
    gemm3_kernel<true, true, false><<<dim3(8, 32, NE), 256, SMEM_DYN>>>(
        x, HDIM, gw, uw, (size_t)IMOE * HDIM, 512, 1024, ggu, 1024);
    act_kernel<<<(T_TOK * TOPK * 512 / 4) / 256, 256>>>(ggu, gh, 1024, 512, 7);
    gemm3_kernel<true, false, true><<<dim3(8, 32, NE), 256, SMEM_DYN>>>(
        gh, 512, dw, dw, (size_t)HDIM * IMOE, 1 << 30, 512, gy, 1024);

    // ---- combine ----
    combine_kernel<<<(T_TOK * 1024 / 4) / 256, 256>>>(out);
}

// round 4
// speedup vs baseline: 2.1800x; 1.0198x over previous
#include <cuda_runtime.h>
#include <cuda_bf16.h>
#include <math.h>
#include <stdint.h>

#define T_TOK 2048
#define HDIM  1024
#define NE    16
#define TOPK  4
#define NG    4
#define TGSEL 2
#define IMOE  512
#define RSCALE 2.5f

typedef __nv_bfloat16 bf16;

// ======================= device scratch ========================================
__device__ int   g_tidx[T_TOK * TOPK];
__device__ float g_tw  [T_TOK * TOPK];
__device__ int   g_cnt [NE];
__device__ int   g_cur [NE];
__device__ int   g_off [NE + 1];
__device__ int   g_ptok[T_TOK * TOPK];
__device__ int   g_pos [T_TOK * TOPK];
__device__ float g_pw  [T_TOK * TOPK];

__device__ float g_gu  [(size_t)T_TOK * TOPK * 1024];   // routed gate|up (fp32)
__device__ float g_y   [(size_t)T_TOK * TOPK * 1024];   // routed down out (weighted)
__device__ float g_gu_sh[(size_t)T_TOK * 2048];         // shared gate|up
__device__ float g_ysh [(size_t)T_TOK * 1024];          // shared down out

// pre-split bf16 hi/lo operand arrays
__device__ bf16 g_xh [T_TOK * HDIM],            g_xl [T_TOK * HDIM];
__device__ bf16 g_gwh[NE * IMOE * HDIM],        g_gwl[NE * IMOE * HDIM];
__device__ bf16 g_uwh[NE * IMOE * HDIM],        g_uwl[NE * IMOE * HDIM];
__device__ bf16 g_dwh[NE * HDIM * IMOE],        g_dwl[NE * HDIM * IMOE];
__device__ bf16 g_sgh[HDIM * 1024],             g_sgl[HDIM * 1024];
__device__ bf16 g_suh[HDIM * 1024],             g_sul[HDIM * 1024];
__device__ bf16 g_sdh[HDIM * 1024],             g_sdl[HDIM * 1024];
__device__ bf16 g_hh [T_TOK * TOPK * IMOE],     g_hl [T_TOK * TOPK * IMOE];
__device__ bf16 g_hsh[T_TOK * 1024],            g_hsl[T_TOK * 1024];

// ======================= routing ==============================================
__global__ void init_kernel() {
    int i = threadIdx.x;
    if (i < NE) { g_cnt[i] = 0; g_cur[i] = 0; }
}

__global__ void router_kernel(const float* __restrict__ x,
                              const float* __restrict__ rw,
                              const float* __restrict__ ebias) {
    int t    = blockIdx.x;
    int w    = threadIdx.x >> 5;
    int lane = threadIdx.x & 31;

    const float* xr = x  + (size_t)t * HDIM;
    const float* wr = rw + (size_t)w * HDIM;
    float s = 0.f;
    for (int k = lane; k < HDIM; k += 32) s += xr[k] * wr[k];
    #pragma unroll
    for (int o = 16; o; o >>= 1) s += __shfl_xor_sync(0xffffffffu, s, o);

    __shared__ float sdot[NE];
    if (lane == 0) sdot[w] = s;
    __syncthreads();

    if (threadIdx.x == 0) {
        float sraw[NE], sc[NE];
        #pragma unroll
        for (int e = 0; e < NE; e++) {
            sraw[e] = 1.f / (1.f + expf(-sdot[e]));
            sc[e]   = sraw[e] + ebias[e];
        }
        float gsc[NG];
        #pragma unroll
        for (int g = 0; g < NG; g++) {
            float m1 = -1e30f, m2 = -1e30f;
            #pragma unroll
            for (int j = 0; j < NE / NG; j++) {
                float v = sc[g * (NE / NG) + j];
                if (v > m1) { m2 = m1; m1 = v; }
                else if (v > m2) { m2 = v; }
            }
            gsc[g] = m1 + m2;
        }
        bool gsel[NG] = {false, false, false, false};
        for (int r = 0; r < TGSEL; r++) {
            int best = -1; float bv = -1e30f;
            for (int g = 0; g < NG; g++)
                if (!gsel[g] && gsc[g] > bv) { bv = gsc[g]; best = g; }
            gsel[best] = true;
        }
        float masked[NE];
        #pragma unroll
        for (int e = 0; e < NE; e++)
            masked[e] = gsel[e / (NE / NG)] ? sc[e] : 0.0f;
        int idx[TOPK]; float tw[TOPK]; float wsum = 0.f;
        for (int r = 0; r < TOPK; r++) {
            int best = 0; float bv = -1e30f;
            for (int e = 0; e < NE; e++)
                if (masked[e] > bv) { bv = masked[e]; best = e; }
            idx[r] = best; tw[r] = sraw[best];
            masked[best] = -1e30f;
            wsum += tw[r];
        }
        float inv = RSCALE / (wsum + 1e-20f);
        for (int r = 0; r < TOPK; r++) {
            g_tidx[t * TOPK + r] = idx[r];
            g_tw  [t * TOPK + r] = tw[r] * inv;
            atomicAdd(&g_cnt[idx[r]], 1);
        }
    }
}

__global__ void scan_kernel() {
    if (threadIdx.x == 0) {
        int acc = 0;
        for (int e = 0; e < NE; e++) { g_off[e] = acc; acc += g_cnt[e]; }
        g_off[NE] = acc;
    }
}

__global__ void scatter_kernel() {
    int s = blockIdx.x * blockDim.x + threadIdx.x;
    if (s >= T_TOK * TOPK) return;
    int e   = g_tidx[s];
    int pos = g_off[e] + atomicAdd(&g_cur[e], 1);
    g_ptok[pos] = s >> 2;
    g_pw  [pos] = g_tw[s];
    g_pos [s]   = pos;
}

// ======================= bf16 hi/lo split helpers ==============================
static __device__ __forceinline__ void split2(float a, float b, uint32_t& h, uint32_t& l) {
    __nv_bfloat162 hb = __float22bfloat162_rn(make_float2(a, b));
    float2 hf = __bfloat1622float2(hb);
    __nv_bfloat162 lb = __float22bfloat162_rn(make_float2(a - hf.x, b - hf.y));
    h = *(uint32_t*)&hb; l = *(uint32_t*)&lb;
}

__global__ void split_kernel(const float4* __restrict__ in,
                             uint2* __restrict__ hi, uint2* __restrict__ lo, int n4) {
    int i = blockIdx.x * blockDim.x + threadIdx.x;
    if (i >= n4) return;
    float4 v = in[i];
    uint32_t h0, l0, h1, l1;
    split2(v.x, v.y, h0, l0);
    split2(v.z, v.w, h1, l1);
    hi[i] = make_uint2(h0, h1);
    lo[i] = make_uint2(l0, l1);
}

// h = silu(g)*u, written directly as bf16 hi/lo
__global__ void act_split_kernel(const float* __restrict__ gu,
                                 uint2* __restrict__ hh, uint2* __restrict__ hl,
                                 int ld, int I, int shf) {
    int idx = blockIdx.x * blockDim.x + threadIdx.x;   // float4 units
    int r = idx >> shf;
    int c4 = idx - (r << shf);
    int c = c4 << 2;
    const float4 g4 = *(const float4*)(gu + (size_t)r * ld + c);
    const float4 u4 = *(const float4*)(gu + (size_t)r * ld + I + c);
    float hx = g4.x * u4.x / (1.f + expf(-g4.x));
    float hy = g4.y * u4.y / (1.f + expf(-g4.y));
    float hz = g4.z * u4.z / (1.f + expf(-g4.z));
    float hw = g4.w * u4.w / (1.f + expf(-g4.w));
    uint32_t h0, l0, h1, l1;
    split2(hx, hy, h0, l0);
    split2(hz, hw, h1, l1);
    size_t o = (size_t)r * (I >> 2) + c4;
    hh[o] = make_uint2(h0, h1);
    hl[o] = make_uint2(l0, l1);
}

// ======================= HMMA 3-split GEMM (cp.async pipelined) ================
// C[128x128] = A[128xK] @ B[128xK]^T. Operands pre-split bf16 hi/lo.
// smem stage: Ah@0 Al@10240 Bh@20480 Bl@30720, 80B padded rows; 3 stages.
#define ROWB   80
#define AH_OFF 0
#define AL_OFF 10240
#define BH_OFF 20480
#define BL_OFF 30720
#define STG_B  40960
#define NSTG   3
#define SMEM_DYN (NSTG * STG_B)

static __device__ __forceinline__ uint32_t smem_u32(const void* p) {
    uint32_t a;
    asm("{ .reg .u64 t; cvta.to.shared.u64 t, %1; cvt.u32.u64 %0, t; }"
        : "=r"(a) : "l"(p));
    return a;
}

#define LDSM_X4(r0, r1, r2, r3, addr) \
    asm volatile("ldmatrix.sync.aligned.m8n8.x4.shared.b16 {%0,%1,%2,%3}, [%4];" \
        : "=r"(r0), "=r"(r1), "=r"(r2), "=r"(r3) : "r"(addr))

#define MMA16816(d, a, b) \
    asm volatile("mma.sync.aligned.m16n8k16.row.col.f32.bf16.bf16.f32 " \
        "{%0,%1,%2,%3},{%4,%5,%6,%7},{%8,%9},{%0,%1,%2,%3};" \
        : "+f"((d)[0]), "+f"((d)[1]), "+f"((d)[2]), "+f"((d)[3]) \
        : "r"((a)[0]), "r"((a)[1]), "r"((a)[2]), "r"((a)[3]), \
          "r"((b)[0]), "r"((b)[1]))

#define CP16(dst, src, sz) \
    asm volatile("cp.async.cg.shared.global [%0], [%1], 16, %2;" \
        :: "r"(dst), "l"(src), "r"(sz) : "memory")
#define CP_COMMIT() asm volatile("cp.async.commit_group;" ::: "memory")
#define CP_WAIT1()  asm volatile("cp.async.wait_group 1;" ::: "memory")

template<bool GROUPED, bool TOKMAP, bool WEIGHT>
__global__ void __launch_bounds__(256)
gemmsp_kernel(const bf16* __restrict__ Ah, const bf16* __restrict__ Al, int lda,
              const bf16* __restrict__ B0h, const bf16* __restrict__ B0l,
              const bf16* __restrict__ B1h, const bf16* __restrict__ B1l,
              size_t b_estride, int nb_half,
              int KD, float* __restrict__ Cout, int ldc)
{
    int e = blockIdx.z;
    int rbeg, rend;
    if (GROUPED) { rbeg = g_off[e]; rend = g_off[e + 1]; }
    else         { rbeg = 0;        rend = T_TOK; }
    int row0 = rbeg + blockIdx.y * 128;
    if (row0 >= rend) return;
    int n0 = blockIdx.x * 128;

    const bf16 *Bh, *Bl; int brow0;
    if (n0 < nb_half) {
        Bh = B0h + (size_t)e * b_estride; Bl = B0l + (size_t)e * b_estride; brow0 = n0;
    } else {
        Bh = B1h + (size_t)e * b_estride; Bl = B1l + (size_t)e * b_estride; brow0 = n0 - nb_half;
    }

    extern __shared__ __align__(16) char dynsmem[];
    uint32_t sbase = smem_u32(dynsmem);

    int tid  = threadIdx.x;
    int lane = tid & 31, wid = tid >> 5;
    int wm = (wid >> 2) * 64;
    int wn = (wid & 3) * 32;

    // ---- staging: thread -> (row = tid>>1, 16-elem half = tid&1) --------------
    int srow = tid >> 1;
    int kh16 = (tid & 1) << 4;           // element offset 0 / 16
    int  arow_s = row0 + srow;
    bool avalid = (arow_s < rend);
    const bf16 *pAh = Ah, *pAl = Al;
    if (avalid) {
        int tokr = TOKMAP ? g_ptok[arow_s] : arow_s;
        pAh = Ah + (size_t)tokr * lda + kh16;
        pAl = Al + (size_t)tokr * lda + kh16;
    }
    const bf16* pBh = Bh + (size_t)(brow0 + srow) * KD + kh16;
    const bf16* pBl = Bl + (size_t)(brow0 + srow) * KD + kh16;
    uint32_t st_off = (uint32_t)(srow * ROWB + (tid & 1) * 32);
    uint32_t asz = avalid ? 16u : 0u;

    // ---- ldmatrix per-lane bases ----------------------------------------------
    int a_r  = wm + (lane & 7) + ((lane >> 3) & 1) * 8;
    int a_k  = ((lane >> 4) & 1) * 8;
    uint32_t a_lm = (uint32_t)(a_r * ROWB + a_k * 2);
    int b_r  = wn + (lane & 7) + ((lane >> 4) & 1) * 8;
    int b_k  = ((lane >> 3) & 1) * 8;
    uint32_t b_lm = (uint32_t)(b_r * ROWB + b_k * 2);

    float acc[4][4][4];
    #pragma unroll
    for (int i = 0; i < 4; i++)
        #pragma unroll
        for (int j = 0; j < 4; j++)
            #pragma unroll
            for (int q = 0; q < 4; q++) acc[i][j][q] = 0.f;

    int nchunk = KD >> 5;

    auto issue = [&](int ch) {
        if (ch < nchunk) {
            uint32_t sb = sbase + (uint32_t)(ch % NSTG) * STG_B;
            int k0 = ch << 5;
            const bf16* sa_h = pAh + k0;
            const bf16* sa_l = pAl + k0;
            const bf16* sb_h = pBh + k0;
            const bf16* sb_l = pBl + k0;
            CP16(sb + AH_OFF + st_off,      sa_h,     asz);
            CP16(sb + AH_OFF + st_off + 16, sa_h + 8, asz);
            CP16(sb + AL_OFF + st_off,      sa_l,     asz);
            CP16(sb + AL_OFF + st_off + 16, sa_l + 8, asz);
            CP16(sb + BH_OFF + st_off,      sb_h,     16u);
            CP16(sb + BH_OFF + st_off + 16, sb_h + 8, 16u);
            CP16(sb + BL_OFF + st_off,      sb_l,     16u);
            CP16(sb + BL_OFF + st_off + 16, sb_l + 8, 16u);
        }
        CP_COMMIT();
    };

    issue(0);
    issue(1);

    for (int ch = 0; ch < nchunk; ch++) {
        CP_WAIT1();
        __syncthreads();

        uint32_t sb = sbase + (uint32_t)(ch % NSTG) * STG_B;
        #pragma unroll
        for (int ks = 0; ks < 2; ks++) {
            uint32_t kso = (uint32_t)(ks * 32);
            uint32_t ah[4][4], al[4][4], bh[4][2], bl[4][2];
            #pragma unroll
            for (int mt = 0; mt < 4; mt++) {
                uint32_t ad = sb + a_lm + (uint32_t)(mt * 16 * ROWB) + kso;
                LDSM_X4(ah[mt][0], ah[mt][1], ah[mt][2], ah[mt][3], ad + AH_OFF);
                LDSM_X4(al[mt][0], al[mt][1], al[mt][2], al[mt][3], ad + AL_OFF);
            }
            #pragma unroll
            for (int nt2 = 0; nt2 < 2; nt2++) {
                uint32_t bd = sb + b_lm + (uint32_t)(nt2 * 16 * ROWB) + kso;
                uint32_t r0, r1, r2, r3;
                LDSM_X4(r0, r1, r2, r3, bd + BH_OFF);
                bh[2 * nt2][0] = r0; bh[2 * nt2][1] = r1;
                bh[2 * nt2 + 1][0] = r2; bh[2 * nt2 + 1][1] = r3;
                LDSM_X4(r0, r1, r2, r3, bd + BL_OFF);
                bl[2 * nt2][0] = r0; bl[2 * nt2][1] = r1;
                bl[2 * nt2 + 1][0] = r2; bl[2 * nt2 + 1][1] = r3;
            }
            // term-major ordering: max ILP between dependent accumulations
            #pragma unroll
            for (int mt = 0; mt < 4; mt++)
                #pragma unroll
                for (int nt = 0; nt < 4; nt++)
                    MMA16816(acc[mt][nt], ah[mt], bh[nt]);
            #pragma unroll
            for (int mt = 0; mt < 4; mt++)
                #pragma unroll
                for (int nt = 0; nt < 4; nt++)
                    MMA16816(acc[mt][nt], al[mt], bh[nt]);
            #pragma unroll
            for (int mt = 0; mt < 4; mt++)
                #pragma unroll
                for (int nt = 0; nt < 4; nt++)
                    MMA16816(acc[mt][nt], ah[mt], bl[nt]);
        }

        if (ch + 1 < nchunk) issue(ch + 2);
    }

    // ---- epilogue ----
    int g = lane >> 2, t4 = lane & 3;
    #pragma unroll
    for (int mt = 0; mt < 4; mt++) {
        int R0 = row0 + wm + mt * 16 + g;
        int R1 = R0 + 8;
        bool v0 = (R0 < rend), v1 = (R1 < rend);
        float w0 = 1.f, w1 = 1.f;
        if (WEIGHT) { if (v0) w0 = g_pw[R0]; if (v1) w1 = g_pw[R1]; }
        #pragma unroll
        for (int nt = 0; nt < 4; nt++) {
            int C = n0 + wn + nt * 8 + t4 * 2;
            if (v0) {
                float2 o = make_float2(acc[mt][nt][0] * w0, acc[mt][nt][1] * w0);
                *(float2*)(Cout + (size_t)R0 * ldc + C) = o;
            }
            if (v1) {
                float2 o = make_float2(acc[mt][nt][2] * w1, acc[mt][nt][3] * w1);
                *(float2*)(Cout + (size_t)R1 * ldc + C) = o;
            }
        }
    }
}

// ======================= combine ===============================================
__global__ void combine_kernel(float* __restrict__ out) {
    int idx = blockIdx.x * blockDim.x + threadIdx.x;
    int t = idx >> 8;
    int c = (idx & 255) << 2;
    float4 acc = *(const float4*)(g_ysh + (size_t)t * 1024 + c);
    #pragma unroll
    for (int r = 0; r < TOPK; r++) {
        int p = g_pos[t * TOPK + r];
        const float4 v = *(const float4*)(g_y + (size_t)p * 1024 + c);
        acc.x += v.x; acc.y += v.y; acc.z += v.z; acc.w += v.w;
    }
    *(float4*)(out + (size_t)t * 1024 + c) = acc;
}

// ======================= launch ================================================
extern "C" void kernel_launch(void* const* d_in, const int* in_sizes, int n_in,
                              void* d_out, int out_size) {
    const float* x   = (const float*)d_in[0];
    const float* rw  = (const float*)d_in[1];
    const float* eb  = (const float*)d_in[2];
    const float* gw  = (const float*)d_in[3];
    const float* uw  = (const float*)d_in[4];
    const float* dw  = (const float*)d_in[5];
    const float* shg = (const float*)d_in[6];
    const float* shu = (const float*)d_in[7];
    const float* shd = (const float*)d_in[8];
    float* out = (float*)d_out;

    cudaFuncSetAttribute(gemmsp_kernel<false, false, false>,
                         cudaFuncAttributeMaxDynamicSharedMemorySize, SMEM_DYN);
    cudaFuncSetAttribute(gemmsp_kernel<true, true, false>,
                         cudaFuncAttributeMaxDynamicSharedMemorySize, SMEM_DYN);
    cudaFuncSetAttribute(gemmsp_kernel<true, false, true>,
                         cudaFuncAttributeMaxDynamicSharedMemorySize, SMEM_DYN);

    // symbol addresses
    float *ggu, *gy, *ggus, *gys;
    bf16 *xh, *xl, *gwh, *gwl, *uwh, *uwl, *dwh, *dwl;
    bf16 *sgh, *sgl, *suh, *sul, *sdh, *sdl, *hh, *hl, *hsh, *hsl;
    cudaGetSymbolAddress((void**)&ggu,  g_gu);
    cudaGetSymbolAddress((void**)&gy,   g_y);
    cudaGetSymbolAddress((void**)&ggus, g_gu_sh);
    cudaGetSymbolAddress((void**)&gys,  g_ysh);
    cudaGetSymbolAddress((void**)&xh,  g_xh);  cudaGetSymbolAddress((void**)&xl,  g_xl);
    cudaGetSymbolAddress((void**)&gwh, g_gwh); cudaGetSymbolAddress((void**)&gwl, g_gwl);
    cudaGetSymbolAddress((void**)&uwh, g_uwh); cudaGetSymbolAddress((void**)&uwl, g_uwl);
    cudaGetSymbolAddress((void**)&dwh, g_dwh); cudaGetSymbolAddress((void**)&dwl, g_dwl);
    cudaGetSymbolAddress((void**)&sgh, g_sgh); cudaGetSymbolAddress((void**)&sgl, g_sgl);
    cudaGetSymbolAddress((void**)&suh, g_suh); cudaGetSymbolAddress((void**)&sul, g_sul);
    cudaGetSymbolAddress((void**)&sdh, g_sdh); cudaGetSymbolAddress((void**)&sdl, g_sdl);
    cudaGetSymbolAddress((void**)&hh,  g_hh);  cudaGetSymbolAddress((void**)&hl,  g_hl);
    cudaGetSymbolAddress((void**)&hsh, g_hsh); cudaGetSymbolAddress((void**)&hsl, g_hsl);

    init_kernel<<<1, 32>>>();
    router_kernel<<<T_TOK, NE * 32>>>(x, rw, eb);
    scan_kernel<<<1, 32>>>();
    scatter_kernel<<<(T_TOK * TOPK + 255) / 256, 256>>>();

    // ---- operand splits ----
    auto spl = [](const float* src, bf16* h, bf16* l, size_t n) {
        int n4 = (int)(n >> 2);
        split_kernel<<<(n4 + 255) / 256, 256>>>((const float4*)src, (uint2*)h, (uint2*)l, n4);
    };
    spl(x,   xh,  xl,  (size_t)T_TOK * HDIM);
    spl(gw,  gwh, gwl, (size_t)NE * IMOE * HDIM);
    spl(uw,  uwh, uwl, (size_t)NE * IMOE * HDIM);
    spl(dw,  dwh, dwl, (size_t)NE * HDIM * IMOE);
    spl(shg, sgh, sgl, (size_t)HDIM * 1024);
    spl(shu, suh, sul, (size_t)HDIM * 1024);
    spl(shd, sdh, sdl, (size_t)HDIM * 1024);

    // ---- shared expert ----
    gemmsp_kernel<false, false, false><<<dim3(16, 16, 1), 256, SMEM_DYN>>>(
        xh, xl, HDIM, sgh, sgl, suh, sul, 0, 1024, 1024, ggus, 2048);
    act_split_kernel<<<(T_TOK * 1024 / 4) / 256, 256>>>(
        ggus, (uint2*)hsh, (uint2*)hsl, 2048, 1024, 8);
    gemmsp_kernel<false, false, false><<<dim3(8, 16, 1), 256, SMEM_DYN>>>(
        hsh, hsl, 1024, sdh, sdl, sdh, sdl, 0, 1 << 30, 1024, gys, 1024);

    // ---- routed experts ----
    gemmsp_kernel<true, true, false><<<dim3(8, 32, NE), 256, SMEM_DYN>>>(
        xh, xl, HDIM, gwh, gwl, uwh, uwl, (size_t)IMOE * HDIM, 512, 1024, ggu, 1024);
    act_split_kernel<<<(T_TOK * TOPK * 512 / 4) / 256, 256>>>(
        ggu, (uint2*)hh, (uint2*)hl, 1024, 512, 7);
    gemmsp_kernel<true, false, true><<<dim3(8, 32, NE), 256, SMEM_DYN>>>(
        hh, hl, 512, dwh, dwl, dwh, dwl, (size_t)HDIM * IMOE, 1 << 30, 512, gy, 1024);

    // ---- combine ----
    combine_kernel<<<(T_TOK * 1024 / 4) / 256, 256>>>(out);
}

// round 8
// speedup vs baseline: 2.8164x; 1.2920x over previous
#include <cuda_runtime.h>
#include <cuda_fp16.h>
#include <math.h>
#include <stdint.h>

#define T_TOK 2048
#define HDIM  1024
#define NE    16
#define TOPK  4
#define NG    4
#define TGSEL 2
#define IMOE  512
#define RSCALE 2.5f

typedef __half fp16;

// ======================= device scratch ========================================
__device__ int   g_tidx[T_TOK * TOPK];
__device__ float g_tw  [T_TOK * TOPK];
__device__ int   g_cnt [NE];
__device__ int   g_cur [NE];
__device__ int   g_off [NE + 1];
__device__ int   g_ptok[T_TOK * TOPK];
__device__ int   g_pos [T_TOK * TOPK];
__device__ float g_pw  [T_TOK * TOPK];

__device__ float g_gu  [(size_t)T_TOK * TOPK * 1024];   // routed gate|up (fp32)
__device__ float g_y   [(size_t)T_TOK * TOPK * 1024];   // routed down out (weighted)
__device__ float g_gu_sh[(size_t)T_TOK * 2048];         // shared gate|up
__device__ float g_ysh [(size_t)T_TOK * 1024];          // shared down out

// A-side operands: fp16 hi + lo split
__device__ fp16 g_xh [T_TOK * HDIM],        g_xl [T_TOK * HDIM];
__device__ fp16 g_hh [T_TOK * TOPK * IMOE], g_hl [T_TOK * TOPK * IMOE];
__device__ fp16 g_hsh[T_TOK * 1024],        g_hsl[T_TOK * 1024];
// B-side operands (weights): fp16 hi only
__device__ fp16 g_gwh[NE * IMOE * HDIM];
__device__ fp16 g_uwh[NE * IMOE * HDIM];
__device__ fp16 g_dwh[NE * HDIM * IMOE];
__device__ fp16 g_sgh[HDIM * 1024];
__device__ fp16 g_suh[HDIM * 1024];
__device__ fp16 g_sdh[HDIM * 1024];

// ======================= routing ==============================================
__global__ void init_kernel() {
    int i = threadIdx.x;
    if (i < NE) { g_cnt[i] = 0; g_cur[i] = 0; }
}

__global__ void router_kernel(const float* __restrict__ x,
                              const float* __restrict__ rw,
                              const float* __restrict__ ebias) {
    int t    = blockIdx.x;
    int w    = threadIdx.x >> 5;
    int lane = threadIdx.x & 31;

    const float* xr = x  + (size_t)t * HDIM;
    const float* wr = rw + (size_t)w * HDIM;
    float s = 0.f;
    for (int k = lane; k < HDIM; k += 32) s += xr[k] * wr[k];
    #pragma unroll
    for (int o = 16; o; o >>= 1) s += __shfl_xor_sync(0xffffffffu, s, o);

    __shared__ float sdot[NE];
    if (lane == 0) sdot[w] = s;
    __syncthreads();

    if (threadIdx.x == 0) {
        float sraw[NE], sc[NE];
        #pragma unroll
        for (int e = 0; e < NE; e++) {
            sraw[e] = 1.f / (1.f + expf(-sdot[e]));
            sc[e]   = sraw[e] + ebias[e];
        }
        float gsc[NG];
        #pragma unroll
        for (int g = 0; g < NG; g++) {
            float m1 = -1e30f, m2 = -1e30f;
            #pragma unroll
            for (int j = 0; j < NE / NG; j++) {
                float v = sc[g * (NE / NG) + j];
                if (v > m1) { m2 = m1; m1 = v; }
                else if (v > m2) { m2 = v; }
            }
            gsc[g] = m1 + m2;
        }
        bool gsel[NG] = {false, false, false, false};
        for (int r = 0; r < TGSEL; r++) {
            int best = -1; float bv = -1e30f;
            for (int g = 0; g < NG; g++)
                if (!gsel[g] && gsc[g] > bv) { bv = gsc[g]; best = g; }
            gsel[best] = true;
        }
        float masked[NE];
        #pragma unroll
        for (int e = 0; e < NE; e++)
            masked[e] = gsel[e / (NE / NG)] ? sc[e] : 0.0f;
        int idx[TOPK]; float tw[TOPK]; float wsum = 0.f;
        for (int r = 0; r < TOPK; r++) {
            int best = 0; float bv = -1e30f;
            for (int e = 0; e < NE; e++)
                if (masked[e] > bv) { bv = masked[e]; best = e; }
            idx[r] = best; tw[r] = sraw[best];
            masked[best] = -1e30f;
            wsum += tw[r];
        }
        float inv = RSCALE / (wsum + 1e-20f);
        for (int r = 0; r < TOPK; r++) {
            g_tidx[t * TOPK + r] = idx[r];
            g_tw  [t * TOPK + r] = tw[r] * inv;
            atomicAdd(&g_cnt[idx[r]], 1);
        }
    }
}

__global__ void scan_kernel() {
    if (threadIdx.x == 0) {
        int acc = 0;
        for (int e = 0; e < NE; e++) { g_off[e] = acc; acc += g_cnt[e]; }
        g_off[NE] = acc;
    }
}

__global__ void scatter_kernel() {
    int s = blockIdx.x * blockDim.x + threadIdx.x;
    if (s >= T_TOK * TOPK) return;
    int e   = g_tidx[s];
    int pos = g_off[e] + atomicAdd(&g_cur[e], 1);
    g_ptok[pos] = s >> 2;
    g_pw  [pos] = g_tw[s];
    g_pos [s]   = pos;
}

// ======================= fp16 split / convert helpers ==========================
static __device__ __forceinline__ void split2h(float a, float b, uint32_t& h, uint32_t& l) {
    __half2 hb = __floats2half2_rn(a, b);
    float2 hf = __half22float2(hb);
    __half2 lb = __floats2half2_rn(a - hf.x, b - hf.y);
    h = *(uint32_t*)&hb; l = *(uint32_t*)&lb;
}

// fp32 -> fp16 hi + lo (for A-side operands)
__global__ void split_kernel(const float4* __restrict__ in,
                             uint2* __restrict__ hi, uint2* __restrict__ lo, int n4) {
    int i = blockIdx.x * blockDim.x + threadIdx.x;
    if (i >= n4) return;
    float4 v = in[i];
    uint32_t h0, l0, h1, l1;
    split2h(v.x, v.y, h0, l0);
    split2h(v.z, v.w, h1, l1);
    hi[i] = make_uint2(h0, h1);
    lo[i] = make_uint2(l0, l1);
}

// fp32 -> fp16 (weights, hi only)
__global__ void cvt_kernel(const float4* __restrict__ in, uint2* __restrict__ hi, int n4) {
    int i = blockIdx.x * blockDim.x + threadIdx.x;
    if (i >= n4) return;
    float4 v = in[i];
    __half2 a = __floats2half2_rn(v.x, v.y);
    __half2 b = __floats2half2_rn(v.z, v.w);
    hi[i] = make_uint2(*(uint32_t*)&a, *(uint32_t*)&b);
}

// h = silu(g)*u, written directly as fp16 hi/lo
__global__ void act_split_kernel(const float* __restrict__ gu,
                                 uint2* __restrict__ hh, uint2* __restrict__ hl,
                                 int ld, int I, int shf) {
    int idx = blockIdx.x * blockDim.x + threadIdx.x;   // float4 units
    int r = idx >> shf;
    int c4 = idx - (r << shf);
    int c = c4 << 2;
    const float4 g4 = *(const float4*)(gu + (size_t)r * ld + c);
    const float4 u4 = *(const float4*)(gu + (size_t)r * ld + I + c);
    float hx = g4.x * u4.x / (1.f + expf(-g4.x));
    float hy = g4.y * u4.y / (1.f + expf(-g4.y));
    float hz = g4.z * u4.z / (1.f + expf(-g4.z));
    float hw = g4.w * u4.w / (1.f + expf(-g4.w));
    uint32_t h0, l0, h1, l1;
    split2h(hx, hy, h0, l0);
    split2h(hz, hw, h1, l1);
    size_t o = (size_t)r * (I >> 2) + c4;
    hh[o] = make_uint2(h0, h1);
    hl[o] = make_uint2(l0, l1);
}

// ======================= HMMA 2-term fp16 GEMM (cp.async, 4-stage) =============
// C[128x128] = A[128xK] @ B[128xK]^T; A split fp16 hi/lo, B fp16.
// D = Ah*Bh + Al*Bh. smem stage: Ah@0 Al@10240 Bh@20480, 80B padded rows.
#define ROWB   80
#define AH_OFF 0
#define AL_OFF 10240
#define BH_OFF 20480
#define STG_B  30720
#define NSTG   4
#define SMEM_DYN (NSTG * STG_B)

static __device__ __forceinline__ uint32_t smem_u32(const void* p) {
    uint32_t a;
    asm("{ .reg .u64 t; cvta.to.shared.u64 t, %1; cvt.u32.u64 %0, t; }"
        : "=r"(a) : "l"(p));
    return a;
}

#define LDSM_X4(r0, r1, r2, r3, addr) \
    asm volatile("ldmatrix.sync.aligned.m8n8.x4.shared.b16 {%0,%1,%2,%3}, [%4];" \
        : "=r"(r0), "=r"(r1), "=r"(r2), "=r"(r3) : "r"(addr))

#define MMA16816F16(d, a, b) \
    asm volatile("mma.sync.aligned.m16n8k16.row.col.f32.f16.f16.f32 " \
        "{%0,%1,%2,%3},{%4,%5,%6,%7},{%8,%9},{%0,%1,%2,%3};" \
        : "+f"((d)[0]), "+f"((d)[1]), "+f"((d)[2]), "+f"((d)[3]) \
        : "r"((a)[0]), "r"((a)[1]), "r"((a)[2]), "r"((a)[3]), \
          "r"((b)[0]), "r"((b)[1]))

#define CP16(dst, src, sz) \
    asm volatile("cp.async.cg.shared.global [%0], [%1], 16, %2;" \
        :: "r"(dst), "l"(src), "r"(sz) : "memory")
#define CP_COMMIT() asm volatile("cp.async.commit_group;" ::: "memory")
#define CP_WAIT2()  asm volatile("cp.async.wait_group 2;" ::: "memory")

template<bool GROUPED, bool TOKMAP, bool WEIGHT>
__global__ void __launch_bounds__(256)
gemmh_kernel(const fp16* __restrict__ Ah, const fp16* __restrict__ Al, int lda,
             const fp16* __restrict__ B0h, const fp16* __restrict__ B1h,
             size_t b_estride, int nb_half,
             int KD, float* __restrict__ Cout, int ldc)
{
    int e = blockIdx.z;
    int rbeg, rend;
    if (GROUPED) { rbeg = g_off[e]; rend = g_off[e + 1]; }
    else         { rbeg = 0;        rend = T_TOK; }
    int row0 = rbeg + blockIdx.y * 128;
    if (row0 >= rend) return;
    int n0 = blockIdx.x * 128;

    const fp16* Bh; int brow0;
    if (n0 < nb_half) { Bh = B0h + (size_t)e * b_estride; brow0 = n0; }
    else              { Bh = B1h + (size_t)e * b_estride; brow0 = n0 - nb_half; }

    extern __shared__ __align__(16) char dynsmem[];
    uint32_t sbase = smem_u32(dynsmem);

    int tid  = threadIdx.x;
    int lane = tid & 31, wid = tid >> 5;
    int wm = (wid >> 2) * 64;
    int wn = (wid & 3) * 32;

    // ---- staging: thread -> (row = tid>>1, 16-elem half = tid&1) --------------
    int srow = tid >> 1;
    int kh16 = (tid & 1) << 4;
    int  arow_s = row0 + srow;
    bool avalid = (arow_s < rend);
    const fp16 *pAh = Ah, *pAl = Al;
    if (avalid) {
        int tokr = TOKMAP ? g_ptok[arow_s] : arow_s;
        pAh = Ah + (size_t)tokr * lda + kh16;
        pAl = Al + (size_t)tokr * lda + kh16;
    }
    const fp16* pBh = Bh + (size_t)(brow0 + srow) * KD + kh16;
    uint32_t st_off = (uint32_t)(srow * ROWB + (tid & 1) * 32);
    uint32_t asz = avalid ? 16u : 0u;

    // ---- ldmatrix per-lane bases ----------------------------------------------
    int a_r  = wm + (lane & 7) + ((lane >> 3) & 1) * 8;
    int a_k  = ((lane >> 4) & 1) * 8;
    uint32_t a_lm = (uint32_t)(a_r * ROWB + a_k * 2);
    int b_r  = wn + (lane & 7) + ((lane >> 4) & 1) * 8;
    int b_k  = ((lane >> 3) & 1) * 8;
    uint32_t b_lm = (uint32_t)(b_r * ROWB + b_k * 2);

    float acc[4][4][4];
    #pragma unroll
    for (int i = 0; i < 4; i++)
        #pragma unroll
        for (int j = 0; j < 4; j++)
            #pragma unroll
            for (int q = 0; q < 4; q++) acc[i][j][q] = 0.f;

    int nchunk = KD >> 5;

    auto issue = [&](int ch) {
        if (ch < nchunk) {
            uint32_t sb = sbase + (uint32_t)(ch % NSTG) * STG_B;
            int k0 = ch << 5;
            const fp16* sa_h = pAh + k0;
            const fp16* sa_l = pAl + k0;
            const fp16* sb_h = pBh + k0;
            CP16(sb + AH_OFF + st_off,      sa_h,     asz);
            CP16(sb + AH_OFF + st_off + 16, sa_h + 8, asz);
            CP16(sb + AL_OFF + st_off,      sa_l,     asz);
            CP16(sb + AL_OFF + st_off + 16, sa_l + 8, asz);
            CP16(sb + BH_OFF + st_off,      sb_h,     16u);
            CP16(sb + BH_OFF + st_off + 16, sb_h + 8, 16u);
        }
        CP_COMMIT();
    };

    issue(0);
    issue(1);
    issue(2);

    for (int ch = 0; ch < nchunk; ch++) {
        CP_WAIT2();
        __syncthreads();

        uint32_t sb = sbase + (uint32_t)(ch % NSTG) * STG_B;
        #pragma unroll
        for (int ks = 0; ks < 2; ks++) {
            uint32_t kso = (uint32_t)(ks * 32);
            uint32_t ah[4][4], al[4][4], bh[4][2];
            #pragma unroll
            for (int mt = 0; mt < 4; mt++) {
                uint32_t ad = sb + a_lm + (uint32_t)(mt * 16 * ROWB) + kso;
                LDSM_X4(ah[mt][0], ah[mt][1], ah[mt][2], ah[mt][3], ad + AH_OFF);
                LDSM_X4(al[mt][0], al[mt][1], al[mt][2], al[mt][3], ad + AL_OFF);
            }
            #pragma unroll
            for (int nt2 = 0; nt2 < 2; nt2++) {
                uint32_t bd = sb + b_lm + (uint32_t)(nt2 * 16 * ROWB) + kso;
                uint32_t r0, r1, r2, r3;
                LDSM_X4(r0, r1, r2, r3, bd + BH_OFF);
                bh[2 * nt2][0] = r0; bh[2 * nt2][1] = r1;
                bh[2 * nt2 + 1][0] = r2; bh[2 * nt2 + 1][1] = r3;
            }
            #pragma unroll
            for (int mt = 0; mt < 4; mt++)
                #pragma unroll
                for (int nt = 0; nt < 4; nt++)
                    MMA16816F16(acc[mt][nt], ah[mt], bh[nt]);
            #pragma unroll
            for (int mt = 0; mt < 4; mt++)
                #pragma unroll
                for (int nt = 0; nt < 4; nt++)
                    MMA16816F16(acc[mt][nt], al[mt], bh[nt]);
        }

        if (ch + 1 < nchunk) issue(ch + 3);
    }

    // ---- epilogue ----
    int g = lane >> 2, t4 = lane & 3;
    #pragma unroll
    for (int mt = 0; mt < 4; mt++) {
        int R0 = row0 + wm + mt * 16 + g;
        int R1 = R0 + 8;
        bool v0 = (R0 < rend), v1 = (R1 < rend);
        float w0 = 1.f, w1 = 1.f;
        if (WEIGHT) { if (v0) w0 = g_pw[R0]; if (v1) w1 = g_pw[R1]; }
        #pragma unroll
        for (int nt = 0; nt < 4; nt++) {
            int C = n0 + wn + nt * 8 + t4 * 2;
            if (v0) {
                float2 o = make_float2(acc[mt][nt][0] * w0, acc[mt][nt][1] * w0);
                *(float2*)(Cout + (size_t)R0 * ldc + C) = o;
            }
            if (v1) {
                float2 o = make_float2(acc[mt][nt][2] * w1, acc[mt][nt][3] * w1);
                *(float2*)(Cout + (size_t)R1 * ldc + C) = o;
            }
        }
    }
}

// ======================= combine ===============================================
__global__ void combine_kernel(float* __restrict__ out) {
    int idx = blockIdx.x * blockDim.x + threadIdx.x;
    int t = idx >> 8;
    int c = (idx & 255) << 2;
    float4 acc = *(const float4*)(g_ysh + (size_t)t * 1024 + c);
    #pragma unroll
    for (int r = 0; r < TOPK; r++) {
        int p = g_pos[t * TOPK + r];
        const float4 v = *(const float4*)(g_y + (size_t)p * 1024 + c);
        acc.x += v.x; acc.y += v.y; acc.z += v.z; acc.w += v.w;
    }
    *(float4*)(out + (size_t)t * 1024 + c) = acc;
}

// ======================= launch ================================================
extern "C" void kernel_launch(void* const* d_in, const int* in_sizes, int n_in,
                              void* d_out, int out_size) {
    const float* x   = (const float*)d_in[0];
    const float* rw  = (const float*)d_in[1];
    const float* eb  = (const float*)d_in[2];
    const float* gw  = (const float*)d_in[3];
    const float* uw  = (const float*)d_in[4];
    const float* dw  = (const float*)d_in[5];
    const float* shg = (const float*)d_in[6];
    const float* shu = (const float*)d_in[7];
    const float* shd = (const float*)d_in[8];
    float* out = (float*)d_out;

    cudaFuncSetAttribute(gemmh_kernel<false, false, false>,
                         cudaFuncAttributeMaxDynamicSharedMemorySize, SMEM_DYN);
    cudaFuncSetAttribute(gemmh_kernel<true, true, false>,
                         cudaFuncAttributeMaxDynamicSharedMemorySize, SMEM_DYN);
    cudaFuncSetAttribute(gemmh_kernel<true, false, true>,
                         cudaFuncAttributeMaxDynamicSharedMemorySize, SMEM_DYN);

    float *ggu, *gy, *ggus, *gys;
    fp16 *xh, *xl, *gwh, *uwh, *dwh, *sgh, *suh, *sdh, *hh, *hl, *hsh, *hsl;
    cudaGetSymbolAddress((void**)&ggu,  g_gu);
    cudaGetSymbolAddress((void**)&gy,   g_y);
    cudaGetSymbolAddress((void**)&ggus, g_gu_sh);
    cudaGetSymbolAddress((void**)&gys,  g_ysh);
    cudaGetSymbolAddress((void**)&xh,  g_xh);  cudaGetSymbolAddress((void**)&xl,  g_xl);
    cudaGetSymbolAddress((void**)&gwh, g_gwh);
    cudaGetSymbolAddress((void**)&uwh, g_uwh);
    cudaGetSymbolAddress((void**)&dwh, g_dwh);
    cudaGetSymbolAddress((void**)&sgh, g_sgh);
    cudaGetSymbolAddress((void**)&suh, g_suh);
    cudaGetSymbolAddress((void**)&sdh, g_sdh);
    cudaGetSymbolAddress((void**)&hh,  g_hh);  cudaGetSymbolAddress((void**)&hl,  g_hl);
    cudaGetSymbolAddress((void**)&hsh, g_hsh); cudaGetSymbolAddress((void**)&hsl, g_hsl);

    init_kernel<<<1, 32>>>();
    router_kernel<<<T_TOK, NE * 32>>>(x, rw, eb);
    scan_kernel<<<1, 32>>>();
    scatter_kernel<<<(T_TOK * TOPK + 255) / 256, 256>>>();

    // ---- operand preprocessing ----
    auto spl = [](const float* src, fp16* h, fp16* l, size_t n) {
        int n4 = (int)(n >> 2);
        split_kernel<<<(n4 + 255) / 256, 256>>>((const float4*)src, (uint2*)h, (uint2*)l, n4);
    };
    auto cvt = [](const float* src, fp16* h, size_t n) {
        int n4 = (int)(n >> 2);
        cvt_kernel<<<(n4 + 255) / 256, 256>>>((const float4*)src, (uint2*)h, n4);
    };
    spl(x,   xh,  xl,  (size_t)T_TOK * HDIM);
    cvt(gw,  gwh, (size_t)NE * IMOE * HDIM);
    cvt(uw,  uwh, (size_t)NE * IMOE * HDIM);
    cvt(dw,  dwh, (size_t)NE * HDIM * IMOE);
    cvt(shg, sgh, (size_t)HDIM * 1024);
    cvt(shu, suh, (size_t)HDIM * 1024);
    cvt(shd, sdh, (size_t)HDIM * 1024);

    // ---- shared expert ----
    gemmh_kernel<false, false, false><<<dim3(16, 16, 1), 256, SMEM_DYN>>>(
        xh, xl, HDIM, sgh, suh, 0, 1024, 1024, ggus, 2048);
    act_split_kernel<<<(T_TOK * 1024 / 4) / 256, 256>>>(
        ggus, (uint2*)hsh, (uint2*)hsl, 2048, 1024, 8);
    gemmh_kernel<false, false, false><<<dim3(8, 16, 1), 256, SMEM_DYN>>>(
        hsh, hsl, 1024, sdh, sdh, 0, 1 << 30, 1024, gys, 1024);

    // ---- routed experts ----
    gemmh_kernel<true, true, false><<<dim3(8, 32, NE), 256, SMEM_DYN>>>(
        xh, xl, HDIM, gwh, uwh, (size_t)IMOE * HDIM, 512, 1024, ggu, 1024);
    act_split_kernel<<<(T_TOK * TOPK * 512 / 4) / 256, 256>>>(
        ggu, (uint2*)hh, (uint2*)hl, 1024, 512, 7);
    gemmh_kernel<true, false, true><<<dim3(8, 32, NE), 256, SMEM_DYN>>>(
        hh, hl, 512, dwh, dwh, (size_t)HDIM * IMOE, 1 << 30, 512, gy, 1024);

    // ---- combine ----
    combine_kernel<<<(T_TOK * 1024 / 4) / 256, 256>>>(out);
}

// round 10
// speedup vs baseline: 4.2916x; 1.5238x over previous
#include <cuda_runtime.h>
#include <cuda_fp16.h>
#include <math.h>
#include <stdint.h>

#define T_TOK 2048
#define HDIM  1024
#define NE    16
#define TOPK  4
#define NG    4
#define TGSEL 2
#define IMOE  512
#define RSCALE 2.5f

typedef __half fp16;

// ======================= device scratch ========================================
__device__ int   g_tidx[T_TOK * TOPK];
__device__ float g_tw  [T_TOK * TOPK];
__device__ int   g_cnt [NE];
__device__ int   g_cur [NE];
__device__ int   g_off [NE + 1];
__device__ int   g_ptok[T_TOK * TOPK];
__device__ int   g_pos [T_TOK * TOPK];
__device__ float g_pw  [T_TOK * TOPK];

__device__ float g_gu  [(size_t)T_TOK * TOPK * 1024];   // routed gate|up (fp32)
__device__ float g_y   [(size_t)T_TOK * TOPK * 1024];   // routed down out (weighted)
__device__ float g_gu_sh[(size_t)T_TOK * 2048];         // shared gate|up
__device__ float g_ysh [(size_t)T_TOK * 1024];          // shared down out

// fp16 operands (single precision term)
__device__ fp16 g_xh [T_TOK * HDIM];
__device__ fp16 g_hh [T_TOK * TOPK * IMOE];
__device__ fp16 g_hsh[T_TOK * 1024];
__device__ fp16 g_gwh[NE * IMOE * HDIM];
__device__ fp16 g_uwh[NE * IMOE * HDIM];
__device__ fp16 g_dwh[NE * HDIM * IMOE];
__device__ fp16 g_sgh[HDIM * 1024];
__device__ fp16 g_suh[HDIM * 1024];
__device__ fp16 g_sdh[HDIM * 1024];

// ======================= routing ==============================================
__global__ void init_kernel() {
    int i = threadIdx.x;
    if (i < NE) { g_cnt[i] = 0; g_cur[i] = 0; }
}

__global__ void router_kernel(const float* __restrict__ x,
                              const float* __restrict__ rw,
                              const float* __restrict__ ebias) {
    int t    = blockIdx.x;
    int w    = threadIdx.x >> 5;
    int lane = threadIdx.x & 31;

    const float* xr = x  + (size_t)t * HDIM;
    const float* wr = rw + (size_t)w * HDIM;
    float s = 0.f;
    for (int k = lane; k < HDIM; k += 32) s += xr[k] * wr[k];
    #pragma unroll
    for (int o = 16; o; o >>= 1) s += __shfl_xor_sync(0xffffffffu, s, o);

    __shared__ float sdot[NE];
    if (lane == 0) sdot[w] = s;
    __syncthreads();

    if (threadIdx.x == 0) {
        float sraw[NE], sc[NE];
        #pragma unroll
        for (int e = 0; e < NE; e++) {
            sraw[e] = 1.f / (1.f + expf(-sdot[e]));
            sc[e]   = sraw[e] + ebias[e];
        }
        float gsc[NG];
        #pragma unroll
        for (int g = 0; g < NG; g++) {
            float m1 = -1e30f, m2 = -1e30f;
            #pragma unroll
            for (int j = 0; j < NE / NG; j++) {
                float v = sc[g * (NE / NG) + j];
                if (v > m1) { m2 = m1; m1 = v; }
                else if (v > m2) { m2 = v; }
            }
            gsc[g] = m1 + m2;
        }
        bool gsel[NG] = {false, false, false, false};
        for (int r = 0; r < TGSEL; r++) {
            int best = -1; float bv = -1e30f;
            for (int g = 0; g < NG; g++)
                if (!gsel[g] && gsc[g] > bv) { bv = gsc[g]; best = g; }
            gsel[best] = true;
        }
        float masked[NE];
        #pragma unroll
        for (int e = 0; e < NE; e++)
            masked[e] = gsel[e / (NE / NG)] ? sc[e] : 0.0f;
        int idx[TOPK]; float tw[TOPK]; float wsum = 0.f;
        for (int r = 0; r < TOPK; r++) {
            int best = 0; float bv = -1e30f;
            for (int e = 0; e < NE; e++)
                if (masked[e] > bv) { bv = masked[e]; best = e; }
            idx[r] = best; tw[r] = sraw[best];
            masked[best] = -1e30f;
            wsum += tw[r];
        }
        float inv = RSCALE / (wsum + 1e-20f);
        for (int r = 0; r < TOPK; r++) {
            g_tidx[t * TOPK + r] = idx[r];
            g_tw  [t * TOPK + r] = tw[r] * inv;
            atomicAdd(&g_cnt[idx[r]], 1);
        }
    }
}

__global__ void scan_kernel() {
    if (threadIdx.x == 0) {
        int acc = 0;
        for (int e = 0; e < NE; e++) { g_off[e] = acc; acc += g_cnt[e]; }
        g_off[NE] = acc;
    }
}

__global__ void scatter_kernel() {
    int s = blockIdx.x * blockDim.x + threadIdx.x;
    if (s >= T_TOK * TOPK) return;
    int e   = g_tidx[s];
    int pos = g_off[e] + atomicAdd(&g_cur[e], 1);
    g_ptok[pos] = s >> 2;
    g_pw  [pos] = g_tw[s];
    g_pos [s]   = pos;
}

// ======================= convert helpers =======================================
// fp32 -> fp16 (round-to-nearest)
__global__ void cvt_kernel(const float4* __restrict__ in, uint2* __restrict__ hi, int n4) {
    int i = blockIdx.x * blockDim.x + threadIdx.x;
    if (i >= n4) return;
    float4 v = in[i];
    __half2 a = __floats2half2_rn(v.x, v.y);
    __half2 b = __floats2half2_rn(v.z, v.w);
    hi[i] = make_uint2(*(uint32_t*)&a, *(uint32_t*)&b);
}

// h = silu(g)*u, written as fp16
__global__ void act_kernel(const float* __restrict__ gu,
                           uint2* __restrict__ hh,
                           int ld, int I, int shf) {
    int idx = blockIdx.x * blockDim.x + threadIdx.x;   // float4 units
    int r = idx >> shf;
    int c4 = idx - (r << shf);
    int c = c4 << 2;
    const float4 g4 = *(const float4*)(gu + (size_t)r * ld + c);
    const float4 u4 = *(const float4*)(gu + (size_t)r * ld + I + c);
    float hx = g4.x * u4.x / (1.f + expf(-g4.x));
    float hy = g4.y * u4.y / (1.f + expf(-g4.y));
    float hz = g4.z * u4.z / (1.f + expf(-g4.z));
    float hw = g4.w * u4.w / (1.f + expf(-g4.w));
    __half2 a = __floats2half2_rn(hx, hy);
    __half2 b = __floats2half2_rn(hz, hw);
    hh[(size_t)r * (I >> 2) + c4] = make_uint2(*(uint32_t*)&a, *(uint32_t*)&b);
}

// ======================= fp16 HMMA GEMM (cp.async, 4-stage, 2 CTA/SM) ==========
// C[128x128] = A[128xK] @ B[128xK]^T, fp16 operands, fp32 accum.
// smem per stage: Ah@0 (10240), Bh@10240 (10240); 80B padded rows.
#define ROWB   80
#define AH_OFF 0
#define BH_OFF 10240
#define STG_B  20480
#define NSTG   4
#define SMEM_DYN (NSTG * STG_B)

static __device__ __forceinline__ uint32_t smem_u32(const void* p) {
    uint32_t a;
    asm("{ .reg .u64 t; cvta.to.shared.u64 t, %1; cvt.u32.u64 %0, t; }"
        : "=r"(a) : "l"(p));
    return a;
}

#define LDSM_X4(r0, r1, r2, r3, addr) \
    asm volatile("ldmatrix.sync.aligned.m8n8.x4.shared.b16 {%0,%1,%2,%3}, [%4];" \
        : "=r"(r0), "=r"(r1), "=r"(r2), "=r"(r3) : "r"(addr))

#define MMA16816F16(d, a, b) \
    asm volatile("mma.sync.aligned.m16n8k16.row.col.f32.f16.f16.f32 " \
        "{%0,%1,%2,%3},{%4,%5,%6,%7},{%8,%9},{%0,%1,%2,%3};" \
        : "+f"((d)[0]), "+f"((d)[1]), "+f"((d)[2]), "+f"((d)[3]) \
        : "r"((a)[0]), "r"((a)[1]), "r"((a)[2]), "r"((a)[3]), \
          "r"((b)[0]), "r"((b)[1]))

#define CP16(dst, src, sz) \
    asm volatile("cp.async.cg.shared.global [%0], [%1], 16, %2;" \
        :: "r"(dst), "l"(src), "r"(sz) : "memory")
#define CP_COMMIT() asm volatile("cp.async.commit_group;" ::: "memory")
#define CP_WAIT2()  asm volatile("cp.async.wait_group 2;" ::: "memory")

template<bool GROUPED, bool TOKMAP, bool WEIGHT>
__global__ void __launch_bounds__(256, 2)
gemmh_kernel(const fp16* __restrict__ Ah, int lda,
             const fp16* __restrict__ B0h, const fp16* __restrict__ B1h,
             size_t b_estride, int nb_half,
             int KD, float* __restrict__ Cout, int ldc)
{
    int e = blockIdx.z;
    int rbeg, rend;
    if (GROUPED) { rbeg = g_off[e]; rend = g_off[e + 1]; }
    else         { rbeg = 0;        rend = T_TOK; }
    int row0 = rbeg + blockIdx.y * 128;
    if (row0 >= rend) return;
    int n0 = blockIdx.x * 128;

    const fp16* Bh; int brow0;
    if (n0 < nb_half) { Bh = B0h + (size_t)e * b_estride; brow0 = n0; }
    else              { Bh = B1h + (size_t)e * b_estride; brow0 = n0 - nb_half; }

    extern __shared__ __align__(16) char dynsmem[];
    uint32_t sbase = smem_u32(dynsmem);

    int tid  = threadIdx.x;
    int lane = tid & 31, wid = tid >> 5;
    int wm = (wid >> 2) * 64;
    int wn = (wid & 3) * 32;

    // ---- staging: thread -> (row = tid>>1, 16-elem half = tid&1) --------------
    int srow = tid >> 1;
    int kh16 = (tid & 1) << 4;
    int  arow_s = row0 + srow;
    bool avalid = (arow_s < rend);
    const fp16* pAh = Ah;
    if (avalid) {
        int tokr = TOKMAP ? g_ptok[arow_s] : arow_s;
        pAh = Ah + (size_t)tokr * lda + kh16;
    }
    const fp16* pBh = Bh + (size_t)(brow0 + srow) * KD + kh16;
    uint32_t st_off = (uint32_t)(srow * ROWB + (tid & 1) * 32);
    uint32_t asz = avalid ? 16u : 0u;

    // ---- ldmatrix per-lane bases ----------------------------------------------
    int a_r  = wm + (lane & 7) + ((lane >> 3) & 1) * 8;
    int a_k  = ((lane >> 4) & 1) * 8;
    uint32_t a_lm = (uint32_t)(a_r * ROWB + a_k * 2);
    int b_r  = wn + (lane & 7) + ((lane >> 4) & 1) * 8;
    int b_k  = ((lane >> 3) & 1) * 8;
    uint32_t b_lm = (uint32_t)(b_r * ROWB + b_k * 2);

    float acc[4][4][4];
    #pragma unroll
    for (int i = 0; i < 4; i++)
        #pragma unroll
        for (int j = 0; j < 4; j++)
            #pragma unroll
            for (int q = 0; q < 4; q++) acc[i][j][q] = 0.f;

    int nchunk = KD >> 5;

    auto issue = [&](int ch) {
        if (ch < nchunk) {
            uint32_t sb = sbase + (uint32_t)(ch % NSTG) * STG_B;
            int k0 = ch << 5;
            const fp16* sa_h = pAh + k0;
            const fp16* sb_h = pBh + k0;
            CP16(sb + AH_OFF + st_off,      sa_h,     asz);
            CP16(sb + AH_OFF + st_off + 16, sa_h + 8, asz);
            CP16(sb + BH_OFF + st_off,      sb_h,     16u);
            CP16(sb + BH_OFF + st_off + 16, sb_h + 8, 16u);
        }
        CP_COMMIT();
    };

    issue(0);
    issue(1);
    issue(2);

    for (int ch = 0; ch < nchunk; ch++) {
        CP_WAIT2();
        __syncthreads();

        uint32_t sb = sbase + (uint32_t)(ch % NSTG) * STG_B;
        #pragma unroll
        for (int ks = 0; ks < 2; ks++) {
            uint32_t kso = (uint32_t)(ks * 32);
            uint32_t ah[4][4], bh[4][2];
            #pragma unroll
            for (int mt = 0; mt < 4; mt++) {
                uint32_t ad = sb + a_lm + (uint32_t)(mt * 16 * ROWB) + kso;
                LDSM_X4(ah[mt][0], ah[mt][1], ah[mt][2], ah[mt][3], ad + AH_OFF);
            }
            #pragma unroll
            for (int nt2 = 0; nt2 < 2; nt2++) {
                uint32_t bd = sb + b_lm + (uint32_t)(nt2 * 16 * ROWB) + kso;
                uint32_t r0, r1, r2, r3;
                LDSM_X4(r0, r1, r2, r3, bd + BH_OFF);
                bh[2 * nt2][0] = r0; bh[2 * nt2][1] = r1;
                bh[2 * nt2 + 1][0] = r2; bh[2 * nt2 + 1][1] = r3;
            }
            #pragma unroll
            for (int mt = 0; mt < 4; mt++)
                #pragma unroll
                for (int nt = 0; nt < 4; nt++)
                    MMA16816F16(acc[mt][nt], ah[mt], bh[nt]);
        }

        if (ch + 1 < nchunk) issue(ch + 3);
    }

    // ---- epilogue ----
    int g = lane >> 2, t4 = lane & 3;
    #pragma unroll
    for (int mt = 0; mt < 4; mt++) {
        int R0 = row0 + wm + mt * 16 + g;
        int R1 = R0 + 8;
        bool v0 = (R0 < rend), v1 = (R1 < rend);
        float w0 = 1.f, w1 = 1.f;
        if (WEIGHT) { if (v0) w0 = g_pw[R0]; if (v1) w1 = g_pw[R1]; }
        #pragma unroll
        for (int nt = 0; nt < 4; nt++) {
            int C = n0 + wn + nt * 8 + t4 * 2;
            if (v0) {
                float2 o = make_float2(acc[mt][nt][0] * w0, acc[mt][nt][1] * w0);
                *(float2*)(Cout + (size_t)R0 * ldc + C) = o;
            }
            if (v1) {
                float2 o = make_float2(acc[mt][nt][2] * w1, acc[mt][nt][3] * w1);
                *(float2*)(Cout + (size_t)R1 * ldc + C) = o;
            }
        }
    }
}

// ======================= combine ===============================================
__global__ void combine_kernel(float* __restrict__ out) {
    int idx = blockIdx.x * blockDim.x + threadIdx.x;
    int t = idx >> 8;
    int c = (idx & 255) << 2;
    float4 acc = *(const float4*)(g_ysh + (size_t)t * 1024 + c);
    #pragma unroll
    for (int r = 0; r < TOPK; r++) {
        int p = g_pos[t * TOPK + r];
        const float4 v = *(const float4*)(g_y + (size_t)p * 1024 + c);
        acc.x += v.x; acc.y += v.y; acc.z += v.z; acc.w += v.w;
    }
    *(float4*)(out + (size_t)t * 1024 + c) = acc;
}

// ======================= launch ================================================
extern "C" void kernel_launch(void* const* d_in, const int* in_sizes, int n_in,
                              void* d_out, int out_size) {
    const float* x   = (const float*)d_in[0];
    const float* rw  = (const float*)d_in[1];
    const float* eb  = (const float*)d_in[2];
    const float* gw  = (const float*)d_in[3];
    const float* uw  = (const float*)d_in[4];
    const float* dw  = (const float*)d_in[5];
    const float* shg = (const float*)d_in[6];
    const float* shu = (const float*)d_in[7];
    const float* shd = (const float*)d_in[8];
    float* out = (float*)d_out;

    cudaFuncSetAttribute(gemmh_kernel<false, false, false>,
                         cudaFuncAttributeMaxDynamicSharedMemorySize, SMEM_DYN);
    cudaFuncSetAttribute(gemmh_kernel<true, true, false>,
                         cudaFuncAttributeMaxDynamicSharedMemorySize, SMEM_DYN);
    cudaFuncSetAttribute(gemmh_kernel<true, false, true>,
                         cudaFuncAttributeMaxDynamicSharedMemorySize, SMEM_DYN);

    float *ggu, *gy, *ggus, *gys;
    fp16 *xh, *gwh, *uwh, *dwh, *sgh, *suh, *sdh, *hh, *hsh;
    cudaGetSymbolAddress((void**)&ggu,  g_gu);
    cudaGetSymbolAddress((void**)&gy,   g_y);
    cudaGetSymbolAddress((void**)&ggus, g_gu_sh);
    cudaGetSymbolAddress((void**)&gys,  g_ysh);
    cudaGetSymbolAddress((void**)&xh,  g_xh);
    cudaGetSymbolAddress((void**)&gwh, g_gwh);
    cudaGetSymbolAddress((void**)&uwh, g_uwh);
    cudaGetSymbolAddress((void**)&dwh, g_dwh);
    cudaGetSymbolAddress((void**)&sgh, g_sgh);
    cudaGetSymbolAddress((void**)&suh, g_suh);
    cudaGetSymbolAddress((void**)&sdh, g_sdh);
    cudaGetSymbolAddress((void**)&hh,  g_hh);
    cudaGetSymbolAddress((void**)&hsh, g_hsh);

    init_kernel<<<1, 32>>>();
    router_kernel<<<T_TOK, NE * 32>>>(x, rw, eb);
    scan_kernel<<<1, 32>>>();
    scatter_kernel<<<(T_TOK * TOPK + 255) / 256, 256>>>();

    // ---- operand preprocessing (fp32 -> fp16) ----
    auto cvt = [](const float* src, fp16* h, size_t n) {
        int n4 = (int)(n >> 2);
        cvt_kernel<<<(n4 + 255) / 256, 256>>>((const float4*)src, (uint2*)h, n4);
    };
    cvt(x,   xh,  (size_t)T_TOK * HDIM);
    cvt(gw,  gwh, (size_t)NE * IMOE * HDIM);
    cvt(uw,  uwh, (size_t)NE * IMOE * HDIM);
    cvt(dw,  dwh, (size_t)NE * HDIM * IMOE);
    cvt(shg, sgh, (size_t)HDIM * 1024);
    cvt(shu, suh, (size_t)HDIM * 1024);
    cvt(shd, sdh, (size_t)HDIM * 1024);

    // ---- shared expert ----
    gemmh_kernel<false, false, false><<<dim3(16, 16, 1), 256, SMEM_DYN>>>(
        xh, HDIM, sgh, suh, 0, 1024, 1024, ggus, 2048);
    act_kernel<<<(T_TOK * 1024 / 4) / 256, 256>>>(
        ggus, (uint2*)hsh, 2048, 1024, 8);
    gemmh_kernel<false, false, false><<<dim3(8, 16, 1), 256, SMEM_DYN>>>(
        hsh, 1024, sdh, sdh, 0, 1 << 30, 1024, gys, 1024);

    // ---- routed experts ----
    gemmh_kernel<true, true, false><<<dim3(8, 16, NE), 256, SMEM_DYN>>>(
        xh, HDIM, gwh, uwh, (size_t)IMOE * HDIM, 512, 1024, ggu, 1024);
    act_kernel<<<(T_TOK * TOPK * 512 / 4) / 256, 256>>>(
        ggu, (uint2*)hh, 1024, 512, 7);
    gemmh_kernel<true, false, true><<<dim3(8, 16, NE), 256, SMEM_DYN>>>(
        hh, 512, dwh, dwh, (size_t)HDIM * IMOE, 1 << 30, 512, gy, 1024);

    // ---- combine ----
    combine_kernel<<<(T_TOK * 1024 / 4) / 256, 256>>>(out);
}

// round 12
// speedup vs baseline: 4.3602x; 1.0160x over previous
#include <cuda_runtime.h>
#include <cuda_fp16.h>
#include <math.h>
#include <stdint.h>

#define T_TOK 2048
#define HDIM  1024
#define NE    16
#define TOPK  4
#define NG    4
#define TGSEL 2
#define IMOE  512
#define RSCALE 2.5f

typedef __half fp16;

// ======================= device scratch ========================================
__device__ int   g_tidx[T_TOK * TOPK];
__device__ float g_tw  [T_TOK * TOPK];
__device__ int   g_cnt [NE];
__device__ int   g_cur [NE];
__device__ int   g_off [NE + 1];
__device__ int   g_ptok[T_TOK * TOPK];
__device__ int   g_pos [T_TOK * TOPK];
__device__ float g_pw  [T_TOK * TOPK];

__device__ float g_y   [(size_t)T_TOK * TOPK * 1024];   // routed down out (weighted)
__device__ float g_ysh [(size_t)T_TOK * 1024];          // shared down out

// fp16 operands
__device__ fp16 g_xh [T_TOK * HDIM];
__device__ fp16 g_hh [T_TOK * TOPK * IMOE];
__device__ fp16 g_hsh[T_TOK * 1024];
__device__ fp16 g_gwh[NE * IMOE * HDIM];
__device__ fp16 g_uwh[NE * IMOE * HDIM];
__device__ fp16 g_dwh[NE * HDIM * IMOE];
__device__ fp16 g_sgh[HDIM * 1024];
__device__ fp16 g_suh[HDIM * 1024];
__device__ fp16 g_sdh[HDIM * 1024];

// ======================= routing ==============================================
__global__ void init_kernel() {
    int i = threadIdx.x;
    if (i < NE) { g_cnt[i] = 0; g_cur[i] = 0; }
}

__global__ void router_kernel(const float* __restrict__ x,
                              const float* __restrict__ rw,
                              const float* __restrict__ ebias) {
    int t    = blockIdx.x;
    int w    = threadIdx.x >> 5;
    int lane = threadIdx.x & 31;

    const float* xr = x  + (size_t)t * HDIM;
    const float* wr = rw + (size_t)w * HDIM;
    float s = 0.f;
    for (int k = lane; k < HDIM; k += 32) s += xr[k] * wr[k];
    #pragma unroll
    for (int o = 16; o; o >>= 1) s += __shfl_xor_sync(0xffffffffu, s, o);

    __shared__ float sdot[NE];
    if (lane == 0) sdot[w] = s;
    __syncthreads();

    if (threadIdx.x == 0) {
        float sraw[NE], sc[NE];
        #pragma unroll
        for (int e = 0; e < NE; e++) {
            sraw[e] = 1.f / (1.f + expf(-sdot[e]));
            sc[e]   = sraw[e] + ebias[e];
        }
        float gsc[NG];
        #pragma unroll
        for (int g = 0; g < NG; g++) {
            float m1 = -1e30f, m2 = -1e30f;
            #pragma unroll
            for (int j = 0; j < NE / NG; j++) {
                float v = sc[g * (NE / NG) + j];
                if (v > m1) { m2 = m1; m1 = v; }
                else if (v > m2) { m2 = v; }
            }
            gsc[g] = m1 + m2;
        }
        bool gsel[NG] = {false, false, false, false};
        for (int r = 0; r < TGSEL; r++) {
            int best = -1; float bv = -1e30f;
            for (int g = 0; g < NG; g++)
                if (!gsel[g] && gsc[g] > bv) { bv = gsc[g]; best = g; }
            gsel[best] = true;
        }
        float masked[NE];
        #pragma unroll
        for (int e = 0; e < NE; e++)
            masked[e] = gsel[e / (NE / NG)] ? sc[e] : 0.0f;
        int idx[TOPK]; float tw[TOPK]; float wsum = 0.f;
        for (int r = 0; r < TOPK; r++) {
            int best = 0; float bv = -1e30f;
            for (int e = 0; e < NE; e++)
                if (masked[e] > bv) { bv = masked[e]; best = e; }
            idx[r] = best; tw[r] = sraw[best];
            masked[best] = -1e30f;
            wsum += tw[r];
        }
        float inv = RSCALE / (wsum + 1e-20f);
        for (int r = 0; r < TOPK; r++) {
            g_tidx[t * TOPK + r] = idx[r];
            g_tw  [t * TOPK + r] = tw[r] * inv;
            atomicAdd(&g_cnt[idx[r]], 1);
        }
    }
}

__global__ void scan_kernel() {
    if (threadIdx.x == 0) {
        int acc = 0;
        for (int e = 0; e < NE; e++) { g_off[e] = acc; acc += g_cnt[e]; }
        g_off[NE] = acc;
    }
}

__global__ void scatter_kernel() {
    int s = blockIdx.x * blockDim.x + threadIdx.x;
    if (s >= T_TOK * TOPK) return;
    int e   = g_tidx[s];
    int pos = g_off[e] + atomicAdd(&g_cur[e], 1);
    g_ptok[pos] = s >> 2;
    g_pw  [pos] = g_tw[s];
    g_pos [s]   = pos;
}

// ======================= convert helper ========================================
__global__ void cvt_kernel(const float4* __restrict__ in, uint2* __restrict__ hi, int n4) {
    int i = blockIdx.x * blockDim.x + threadIdx.x;
    if (i >= n4) return;
    float4 v = in[i];
    __half2 a = __floats2half2_rn(v.x, v.y);
    __half2 b = __floats2half2_rn(v.z, v.w);
    hi[i] = make_uint2(*(uint32_t*)&a, *(uint32_t*)&b);
}

// ======================= shared GEMM machinery =================================
#define ROWB   80
#define AH_OFF 0
#define BH_OFF 10240
#define STG_B  20480
#define NSTG   4
#define SMEM_DYN (NSTG * STG_B)
#define EP_LD  132   // epilogue fp32 tile row stride (floats)

static __device__ __forceinline__ uint32_t smem_u32(const void* p) {
    uint32_t a;
    asm("{ .reg .u64 t; cvta.to.shared.u64 t, %1; cvt.u32.u64 %0, t; }"
        : "=r"(a) : "l"(p));
    return a;
}

#define LDSM_X4(r0, r1, r2, r3, addr) \
    asm volatile("ldmatrix.sync.aligned.m8n8.x4.shared.b16 {%0,%1,%2,%3}, [%4];" \
        : "=r"(r0), "=r"(r1), "=r"(r2), "=r"(r3) : "r"(addr))

#define MMA16816F16(d, a, b) \
    asm volatile("mma.sync.aligned.m16n8k16.row.col.f32.f16.f16.f32 " \
        "{%0,%1,%2,%3},{%4,%5,%6,%7},{%8,%9},{%0,%1,%2,%3};" \
        : "+f"((d)[0]), "+f"((d)[1]), "+f"((d)[2]), "+f"((d)[3]) \
        : "r"((a)[0]), "r"((a)[1]), "r"((a)[2]), "r"((a)[3]), \
          "r"((b)[0]), "r"((b)[1]))

#define CP16(dst, src, sz) \
    asm volatile("cp.async.cg.shared.global [%0], [%1], 16, %2;" \
        :: "r"(dst), "l"(src), "r"(sz) : "memory")
#define CP_COMMIT() asm volatile("cp.async.commit_group;" ::: "memory")
#define CP_WAIT2()  asm volatile("cp.async.wait_group 2;" ::: "memory")
#define CP_WAIT0()  asm volatile("cp.async.wait_group 0;" ::: "memory")

// ======================= gate+up GEMM with fused SwiGLU ========================
// B smem tile: rows 0-63 = gate weight rows n0h..n0h+63, rows 64-127 = up rows.
// C cols 0-63 = g, cols 64-127 = u (for the same channels). Epilogue stages the
// fp32 C tile through smem, computes silu(g)*u, stores fp16 h directly.
template<bool GROUPED, bool TOKMAP>
__global__ void __launch_bounds__(256, 2)
gemmh_act_kernel(const fp16* __restrict__ Ah, int lda,
                 const fp16* __restrict__ Bg, const fp16* __restrict__ Bu,
                 size_t b_estride,
                 int KD, fp16* __restrict__ Hout, int ldh)
{
    int e = blockIdx.z;
    int rbeg, rend;
    if (GROUPED) { rbeg = g_off[e]; rend = g_off[e + 1]; }
    else         { rbeg = 0;        rend = T_TOK; }
    int row0 = rbeg + blockIdx.y * 128;
    if (row0 >= rend) return;
    int n0h = blockIdx.x * 64;    // intermediate channel block

    const fp16* Bge = Bg + (size_t)e * b_estride;
    const fp16* Bue = Bu + (size_t)e * b_estride;

    extern __shared__ __align__(16) char dynsmem[];
    uint32_t sbase = smem_u32(dynsmem);

    int tid  = threadIdx.x;
    int lane = tid & 31, wid = tid >> 5;
    int wm = (wid >> 2) * 64;
    int wn = (wid & 3) * 32;

    // staging
    int srow = tid >> 1;
    int kh16 = (tid & 1) << 4;
    int  arow_s = row0 + srow;
    bool avalid = (arow_s < rend);
    const fp16* pAh = Ah;
    if (avalid) {
        int tokr = TOKMAP ? g_ptok[arow_s] : arow_s;
        pAh = Ah + (size_t)tokr * lda + kh16;
    }
    const fp16* pBh = (srow < 64)
        ? Bge + (size_t)(n0h + srow) * KD + kh16
        : Bue + (size_t)(n0h + srow - 64) * KD + kh16;
    uint32_t st_off = (uint32_t)(srow * ROWB + (tid & 1) * 32);
    uint32_t asz = avalid ? 16u : 0u;

    // ldmatrix bases
    int a_r  = wm + (lane & 7) + ((lane >> 3) & 1) * 8;
    int a_k  = ((lane >> 4) & 1) * 8;
    uint32_t a_lm = (uint32_t)(a_r * ROWB + a_k * 2);
    int b_r  = wn + (lane & 7) + ((lane >> 4) & 1) * 8;
    int b_k  = ((lane >> 3) & 1) * 8;
    uint32_t b_lm = (uint32_t)(b_r * ROWB + b_k * 2);

    float acc[4][4][4];
    #pragma unroll
    for (int i = 0; i < 4; i++)
        #pragma unroll
        for (int j = 0; j < 4; j++)
            #pragma unroll
            for (int q = 0; q < 4; q++) acc[i][j][q] = 0.f;

    int nchunk = KD >> 5;

    auto issue = [&](int ch) {
        if (ch < nchunk) {
            uint32_t sb = sbase + (uint32_t)(ch % NSTG) * STG_B;
            int k0 = ch << 5;
            const fp16* sa_h = pAh + k0;
            const fp16* sb_h = pBh + k0;
            CP16(sb + AH_OFF + st_off,      sa_h,     asz);
            CP16(sb + AH_OFF + st_off + 16, sa_h + 8, asz);
            CP16(sb + BH_OFF + st_off,      sb_h,     16u);
            CP16(sb + BH_OFF + st_off + 16, sb_h + 8, 16u);
        }
        CP_COMMIT();
    };

    issue(0);
    issue(1);
    issue(2);

    for (int ch = 0; ch < nchunk; ch++) {
        CP_WAIT2();
        __syncthreads();

        uint32_t sb = sbase + (uint32_t)(ch % NSTG) * STG_B;
        #pragma unroll
        for (int ks = 0; ks < 2; ks++) {
            uint32_t kso = (uint32_t)(ks * 32);
            uint32_t ah[4][4], bh[4][2];
            #pragma unroll
            for (int mt = 0; mt < 4; mt++) {
                uint32_t ad = sb + a_lm + (uint32_t)(mt * 16 * ROWB) + kso;
                LDSM_X4(ah[mt][0], ah[mt][1], ah[mt][2], ah[mt][3], ad + AH_OFF);
            }
            #pragma unroll
            for (int nt2 = 0; nt2 < 2; nt2++) {
                uint32_t bd = sb + b_lm + (uint32_t)(nt2 * 16 * ROWB) + kso;
                uint32_t r0, r1, r2, r3;
                LDSM_X4(r0, r1, r2, r3, bd + BH_OFF);
                bh[2 * nt2][0] = r0; bh[2 * nt2][1] = r1;
                bh[2 * nt2 + 1][0] = r2; bh[2 * nt2 + 1][1] = r3;
            }
            #pragma unroll
            for (int mt = 0; mt < 4; mt++)
                #pragma unroll
                for (int nt = 0; nt < 4; nt++)
                    MMA16816F16(acc[mt][nt], ah[mt], bh[nt]);
        }

        if (ch + 1 < nchunk) issue(ch + 3);
    }

    // ---- fused SwiGLU epilogue via smem staging --------------------------------
    CP_WAIT0();
    __syncthreads();                       // all smem reads done; safe to reuse

    float* eps = (float*)dynsmem;          // 128 x EP_LD fp32
    int gr = lane >> 2, t4 = lane & 3;
    #pragma unroll
    for (int mt = 0; mt < 4; mt++) {
        int L0 = wm + mt * 16 + gr;        // local rows
        int L1 = L0 + 8;
        #pragma unroll
        for (int nt = 0; nt < 4; nt++) {
            int C = wn + nt * 8 + t4 * 2;
            *(float2*)(eps + L0 * EP_LD + C) = make_float2(acc[mt][nt][0], acc[mt][nt][1]);
            *(float2*)(eps + L1 * EP_LD + C) = make_float2(acc[mt][nt][2], acc[mt][nt][3]);
        }
    }
    __syncthreads();

    {
        int r  = tid >> 1;                 // local row 0..127
        int cb = (tid & 1) * 32;           // h column sub-block
        int R  = row0 + r;
        if (R < rend) {
            fp16* ho = Hout + (size_t)R * ldh + n0h + cb;
            #pragma unroll
            for (int i = 0; i < 8; i++) {
                float4 gv = *(float4*)(eps + r * EP_LD + cb + 4 * i);
                float4 uv = *(float4*)(eps + r * EP_LD + 64 + cb + 4 * i);
                float h0 = gv.x * uv.x / (1.f + expf(-gv.x));
                float h1 = gv.y * uv.y / (1.f + expf(-gv.y));
                float h2 = gv.z * uv.z / (1.f + expf(-gv.z));
                float h3 = gv.w * uv.w / (1.f + expf(-gv.w));
                __half2 p0 = __floats2half2_rn(h0, h1);
                __half2 p1 = __floats2half2_rn(h2, h3);
                *(uint2*)(ho + 4 * i) = make_uint2(*(uint32_t*)&p0, *(uint32_t*)&p1);
            }
        }
    }
}

// ======================= down GEMM (fp32 out, optional weight) =================
template<bool GROUPED, bool TOKMAP, bool WEIGHT>
__global__ void __launch_bounds__(256, 2)
gemmh_kernel(const fp16* __restrict__ Ah, int lda,
             const fp16* __restrict__ B0h, size_t b_estride,
             int KD, float* __restrict__ Cout, int ldc)
{
    int e = blockIdx.z;
    int rbeg, rend;
    if (GROUPED) { rbeg = g_off[e]; rend = g_off[e + 1]; }
    else         { rbeg = 0;        rend = T_TOK; }
    int row0 = rbeg + blockIdx.y * 128;
    if (row0 >= rend) return;
    int n0 = blockIdx.x * 128;

    const fp16* Bh = B0h + (size_t)e * b_estride;
    int brow0 = n0;

    extern __shared__ __align__(16) char dynsmem[];
    uint32_t sbase = smem_u32(dynsmem);

    int tid  = threadIdx.x;
    int lane = tid & 31, wid = tid >> 5;
    int wm = (wid >> 2) * 64;
    int wn = (wid & 3) * 32;

    int srow = tid >> 1;
    int kh16 = (tid & 1) << 4;
    int  arow_s = row0 + srow;
    bool avalid = (arow_s < rend);
    const fp16* pAh = Ah;
    if (avalid) {
        int tokr = TOKMAP ? g_ptok[arow_s] : arow_s;
        pAh = Ah + (size_t)tokr * lda + kh16;
    }
    const fp16* pBh = Bh + (size_t)(brow0 + srow) * KD + kh16;
    uint32_t st_off = (uint32_t)(srow * ROWB + (tid & 1) * 32);
    uint32_t asz = avalid ? 16u : 0u;

    int a_r  = wm + (lane & 7) + ((lane >> 3) & 1) * 8;
    int a_k  = ((lane >> 4) & 1) * 8;
    uint32_t a_lm = (uint32_t)(a_r * ROWB + a_k * 2);
    int b_r  = wn + (lane & 7) + ((lane >> 4) & 1) * 8;
    int b_k  = ((lane >> 3) & 1) * 8;
    uint32_t b_lm = (uint32_t)(b_r * ROWB + b_k * 2);

    float acc[4][4][4];
    #pragma unroll
    for (int i = 0; i < 4; i++)
        #pragma unroll
        for (int j = 0; j < 4; j++)
            #pragma unroll
            for (int q = 0; q < 4; q++) acc[i][j][q] = 0.f;

    int nchunk = KD >> 5;

    auto issue = [&](int ch) {
        if (ch < nchunk) {
            uint32_t sb = sbase + (uint32_t)(ch % NSTG) * STG_B;
            int k0 = ch << 5;
            const fp16* sa_h = pAh + k0;
            const fp16* sb_h = pBh + k0;
            CP16(sb + AH_OFF + st_off,      sa_h,     asz);
            CP16(sb + AH_OFF + st_off + 16, sa_h + 8, asz);
            CP16(sb + BH_OFF + st_off,      sb_h,     16u);
            CP16(sb + BH_OFF + st_off + 16, sb_h + 8, 16u);
        }
        CP_COMMIT();
    };

    issue(0);
    issue(1);
    issue(2);

    for (int ch = 0; ch < nchunk; ch++) {
        CP_WAIT2();
        __syncthreads();

        uint32_t sb = sbase + (uint32_t)(ch % NSTG) * STG_B;
        #pragma unroll
        for (int ks = 0; ks < 2; ks++) {
            uint32_t kso = (uint32_t)(ks * 32);
            uint32_t ah[4][4], bh[4][2];
            #pragma unroll
            for (int mt = 0; mt < 4; mt++) {
                uint32_t ad = sb + a_lm + (uint32_t)(mt * 16 * ROWB) + kso;
                LDSM_X4(ah[mt][0], ah[mt][1], ah[mt][2], ah[mt][3], ad + AH_OFF);
            }
            #pragma unroll
            for (int nt2 = 0; nt2 < 2; nt2++) {
                uint32_t bd = sb + b_lm + (uint32_t)(nt2 * 16 * ROWB) + kso;
                uint32_t r0, r1, r2, r3;
                LDSM_X4(r0, r1, r2, r3, bd + BH_OFF);
                bh[2 * nt2][0] = r0; bh[2 * nt2][1] = r1;
                bh[2 * nt2 + 1][0] = r2; bh[2 * nt2 + 1][1] = r3;
            }
            #pragma unroll
            for (int mt = 0; mt < 4; mt++)
                #pragma unroll
                for (int nt = 0; nt < 4; nt++)
                    MMA16816F16(acc[mt][nt], ah[mt], bh[nt]);
        }

        if (ch + 1 < nchunk) issue(ch + 3);
    }

    // epilogue
    int g = lane >> 2, t4 = lane & 3;
    #pragma unroll
    for (int mt = 0; mt < 4; mt++) {
        int R0 = row0 + wm + mt * 16 + g;
        int R1 = R0 + 8;
        bool v0 = (R0 < rend), v1 = (R1 < rend);
        float w0 = 1.f, w1 = 1.f;
        if (WEIGHT) { if (v0) w0 = g_pw[R0]; if (v1) w1 = g_pw[R1]; }
        #pragma unroll
        for (int nt = 0; nt < 4; nt++) {
            int C = n0 + wn + nt * 8 + t4 * 2;
            if (v0) {
                float2 o = make_float2(acc[mt][nt][0] * w0, acc[mt][nt][1] * w0);
                *(float2*)(Cout + (size_t)R0 * ldc + C) = o;
            }
            if (v1) {
                float2 o = make_float2(acc[mt][nt][2] * w1, acc[mt][nt][3] * w1);
                *(float2*)(Cout + (size_t)R1 * ldc + C) = o;
            }
        }
    }
}

// ======================= combine ===============================================
__global__ void combine_kernel(float* __restrict__ out) {
    int idx = blockIdx.x * blockDim.x + threadIdx.x;
    int t = idx >> 8;
    int c = (idx & 255) << 2;
    float4 acc = *(const float4*)(g_ysh + (size_t)t * 1024 + c);
    #pragma unroll
    for (int r = 0; r < TOPK; r++) {
        int p = g_pos[t * TOPK + r];
        const float4 v = *(const float4*)(g_y + (size_t)p * 1024 + c);
        acc.x += v.x; acc.y += v.y; acc.z += v.z; acc.w += v.w;
    }
    *(float4*)(out + (size_t)t * 1024 + c) = acc;
}

// ======================= launch ================================================
extern "C" void kernel_launch(void* const* d_in, const int* in_sizes, int n_in,
                              void* d_out, int out_size) {
    const float* x   = (const float*)d_in[0];
    const float* rw  = (const float*)d_in[1];
    const float* eb  = (const float*)d_in[2];
    const float* gw  = (const float*)d_in[3];
    const float* uw  = (const float*)d_in[4];
    const float* dw  = (const float*)d_in[5];
    const float* shg = (const float*)d_in[6];
    const float* shu = (const float*)d_in[7];
    const float* shd = (const float*)d_in[8];
    float* out = (float*)d_out;

    cudaFuncSetAttribute(gemmh_act_kernel<false, false>,
                         cudaFuncAttributeMaxDynamicSharedMemorySize, SMEM_DYN);
    cudaFuncSetAttribute(gemmh_act_kernel<true, true>,
                         cudaFuncAttributeMaxDynamicSharedMemorySize, SMEM_DYN);
    cudaFuncSetAttribute(gemmh_kernel<false, false, false>,
                         cudaFuncAttributeMaxDynamicSharedMemorySize, SMEM_DYN);
    cudaFuncSetAttribute(gemmh_kernel<true, false, true>,
                         cudaFuncAttributeMaxDynamicSharedMemorySize, SMEM_DYN);

    float *gy, *gys;
    fp16 *xh, *gwh, *uwh, *dwh, *sgh, *suh, *sdh, *hh, *hsh;
    cudaGetSymbolAddress((void**)&gy,   g_y);
    cudaGetSymbolAddress((void**)&gys,  g_ysh);
    cudaGetSymbolAddress((void**)&xh,  g_xh);
    cudaGetSymbolAddress((void**)&gwh, g_gwh);
    cudaGetSymbolAddress((void**)&uwh, g_uwh);
    cudaGetSymbolAddress((void**)&dwh, g_dwh);
    cudaGetSymbolAddress((void**)&sgh, g_sgh);
    cudaGetSymbolAddress((void**)&suh, g_suh);
    cudaGetSymbolAddress((void**)&sdh, g_sdh);
    cudaGetSymbolAddress((void**)&hh,  g_hh);
    cudaGetSymbolAddress((void**)&hsh, g_hsh);

    init_kernel<<<1, 32>>>();
    router_kernel<<<T_TOK, NE * 32>>>(x, rw, eb);
    scan_kernel<<<1, 32>>>();
    scatter_kernel<<<(T_TOK * TOPK + 255) / 256, 256>>>();

    // ---- operand preprocessing (fp32 -> fp16) ----
    auto cvt = [](const float* src, fp16* h, size_t n) {
        int n4 = (int)(n >> 2);
        cvt_kernel<<<(n4 + 255) / 256, 256>>>((const float4*)src, (uint2*)h, n4);
    };
    cvt(x,   xh,  (size_t)T_TOK * HDIM);
    cvt(gw,  gwh, (size_t)NE * IMOE * HDIM);
    cvt(uw,  uwh, (size_t)NE * IMOE * HDIM);
    cvt(dw,  dwh, (size_t)NE * HDIM * IMOE);
    cvt(shg, sgh, (size_t)HDIM * 1024);
    cvt(shu, suh, (size_t)HDIM * 1024);
    cvt(shd, sdh, (size_t)HDIM * 1024);

    // ---- shared expert: fused gate+up+act, then down ----
    gemmh_act_kernel<false, false><<<dim3(16, 16, 1), 256, SMEM_DYN>>>(
        xh, HDIM, sgh, suh, 0, 1024, hsh, 1024);
    gemmh_kernel<false, false, false><<<dim3(8, 16, 1), 256, SMEM_DYN>>>(
        hsh, 1024, sdh, 0, 1024, gys, 1024);

    // ---- routed experts: fused gate+up+act, then down ----
    gemmh_act_kernel<true, true><<<dim3(8, 16, NE), 256, SMEM_DYN>>>(
        xh, HDIM, gwh, uwh, (size_t)IMOE * HDIM, 1024, hh, 512);
    gemmh_kernel<true, false, true><<<dim3(8, 16, NE), 256, SMEM_DYN>>>(
        hh, 512, dwh, (size_t)HDIM * IMOE, 512, gy, 1024);

    // ---- combine ----
    combine_kernel<<<(T_TOK * 1024 / 4) / 256, 256>>>(out);
}

// round 13
// speedup vs baseline: 4.5768x; 1.0497x over previous
#include <cuda_runtime.h>
#include <cuda_fp16.h>
#include <math.h>
#include <stdint.h>

#define T_TOK 2048
#define HDIM  1024
#define NE    16
#define TOPK  4
#define NG    4
#define TGSEL 2
#define IMOE  512
#define RSCALE 2.5f

typedef __half fp16;

// ======================= device scratch ========================================
__device__ int   g_tidx[T_TOK * TOPK];
__device__ float g_tw  [T_TOK * TOPK];
__device__ int   g_cnt [NE];
__device__ int   g_cur [NE];
__device__ int   g_off [NE + 1];
__device__ int   g_ptok[T_TOK * TOPK];
__device__ int   g_pos [T_TOK * TOPK];
__device__ float g_pw  [T_TOK * TOPK];

__device__ fp16  g_yh [(size_t)T_TOK * TOPK * 1024];   // routed down out (weighted, fp16)
__device__ float g_ysh[(size_t)T_TOK * 1024];           // shared down out (fp32)

// fp16 operands
__device__ fp16 g_xh [T_TOK * HDIM];
__device__ fp16 g_hh [T_TOK * TOPK * IMOE];
__device__ fp16 g_hsh[T_TOK * 1024];
__device__ fp16 g_gwh[NE * IMOE * HDIM];
__device__ fp16 g_uwh[NE * IMOE * HDIM];
__device__ fp16 g_dwh[NE * HDIM * IMOE];
__device__ fp16 g_sgh[HDIM * 1024];
__device__ fp16 g_suh[HDIM * 1024];
__device__ fp16 g_sdh[HDIM * 1024];

// ======================= fused convert (all operands) + counter init ===========
#define NSEG 7
struct CvtArgs {
    const float4* src[NSEG];
    uint2*        dst[NSEG];
    int           cum[NSEG];   // cumulative start (in float4 units)
};

__global__ void cvt_all_kernel(CvtArgs a, int total) {
    if (blockIdx.x == 0 && threadIdx.x < NE) {
        g_cnt[threadIdx.x] = 0;
        g_cur[threadIdx.x] = 0;
    }
    int i = blockIdx.x * blockDim.x + threadIdx.x;
    if (i >= total) return;
    int s = 0;
    #pragma unroll
    for (int k = 1; k < NSEG; k++) if (i >= a.cum[k]) s = k;
    int off = i - a.cum[s];
    float4 v = a.src[s][off];
    __half2 p0 = __floats2half2_rn(v.x, v.y);
    __half2 p1 = __floats2half2_rn(v.z, v.w);
    a.dst[s][off] = make_uint2(*(uint32_t*)&p0, *(uint32_t*)&p1);
}

// ======================= routing ==============================================
__global__ void router_kernel(const float* __restrict__ x,
                              const float* __restrict__ rw,
                              const float* __restrict__ ebias) {
    int t    = blockIdx.x;
    int w    = threadIdx.x >> 5;
    int lane = threadIdx.x & 31;

    const float* xr = x  + (size_t)t * HDIM;
    const float* wr = rw + (size_t)w * HDIM;
    float s = 0.f;
    for (int k = lane; k < HDIM; k += 32) s += xr[k] * wr[k];
    #pragma unroll
    for (int o = 16; o; o >>= 1) s += __shfl_xor_sync(0xffffffffu, s, o);

    __shared__ float sdot[NE];
    if (lane == 0) sdot[w] = s;
    __syncthreads();

    if (threadIdx.x == 0) {
        float sraw[NE], sc[NE];
        #pragma unroll
        for (int e = 0; e < NE; e++) {
            sraw[e] = 1.f / (1.f + expf(-sdot[e]));
            sc[e]   = sraw[e] + ebias[e];
        }
        float gsc[NG];
        #pragma unroll
        for (int g = 0; g < NG; g++) {
            float m1 = -1e30f, m2 = -1e30f;
            #pragma unroll
            for (int j = 0; j < NE / NG; j++) {
                float v = sc[g * (NE / NG) + j];
                if (v > m1) { m2 = m1; m1 = v; }
                else if (v > m2) { m2 = v; }
            }
            gsc[g] = m1 + m2;
        }
        bool gsel[NG] = {false, false, false, false};
        for (int r = 0; r < TGSEL; r++) {
            int best = -1; float bv = -1e30f;
            for (int g = 0; g < NG; g++)
                if (!gsel[g] && gsc[g] > bv) { bv = gsc[g]; best = g; }
            gsel[best] = true;
        }
        float masked[NE];
        #pragma unroll
        for (int e = 0; e < NE; e++)
            masked[e] = gsel[e / (NE / NG)] ? sc[e] : 0.0f;
        int idx[TOPK]; float tw[TOPK]; float wsum = 0.f;
        for (int r = 0; r < TOPK; r++) {
            int best = 0; float bv = -1e30f;
            for (int e = 0; e < NE; e++)
                if (masked[e] > bv) { bv = masked[e]; best = e; }
            idx[r] = best; tw[r] = sraw[best];
            masked[best] = -1e30f;
            wsum += tw[r];
        }
        float inv = RSCALE / (wsum + 1e-20f);
        for (int r = 0; r < TOPK; r++) {
            g_tidx[t * TOPK + r] = idx[r];
            g_tw  [t * TOPK + r] = tw[r] * inv;
            atomicAdd(&g_cnt[idx[r]], 1);
        }
    }
}

__global__ void scan_kernel() {
    if (threadIdx.x == 0) {
        int acc = 0;
        for (int e = 0; e < NE; e++) { g_off[e] = acc; acc += g_cnt[e]; }
        g_off[NE] = acc;
    }
}

__global__ void scatter_kernel() {
    int s = blockIdx.x * blockDim.x + threadIdx.x;
    if (s >= T_TOK * TOPK) return;
    int e   = g_tidx[s];
    int pos = g_off[e] + atomicAdd(&g_cur[e], 1);
    g_ptok[pos] = s >> 2;
    g_pw  [pos] = g_tw[s];
    g_pos [s]   = pos;
}

// ======================= shared GEMM machinery =================================
#define ROWB   80
#define AH_OFF 0
#define BH_OFF 10240
#define STG_B  20480
#define NSTG   4
#define SMEM_DYN (NSTG * STG_B)
#define EP_LD  132   // epilogue fp32 tile row stride (floats)

static __device__ __forceinline__ uint32_t smem_u32(const void* p) {
    uint32_t a;
    asm("{ .reg .u64 t; cvta.to.shared.u64 t, %1; cvt.u32.u64 %0, t; }"
        : "=r"(a) : "l"(p));
    return a;
}

#define LDSM_X4(r0, r1, r2, r3, addr) \
    asm volatile("ldmatrix.sync.aligned.m8n8.x4.shared.b16 {%0,%1,%2,%3}, [%4];" \
        : "=r"(r0), "=r"(r1), "=r"(r2), "=r"(r3) : "r"(addr))

#define MMA16816F16(d, a, b) \
    asm volatile("mma.sync.aligned.m16n8k16.row.col.f32.f16.f16.f32 " \
        "{%0,%1,%2,%3},{%4,%5,%6,%7},{%8,%9},{%0,%1,%2,%3};" \
        : "+f"((d)[0]), "+f"((d)[1]), "+f"((d)[2]), "+f"((d)[3]) \
        : "r"((a)[0]), "r"((a)[1]), "r"((a)[2]), "r"((a)[3]), \
          "r"((b)[0]), "r"((b)[1]))

#define CP16(dst, src, sz) \
    asm volatile("cp.async.cg.shared.global [%0], [%1], 16, %2;" \
        :: "r"(dst), "l"(src), "r"(sz) : "memory")
#define CP_COMMIT() asm volatile("cp.async.commit_group;" ::: "memory")
#define CP_WAIT2()  asm volatile("cp.async.wait_group 2;" ::: "memory")
#define CP_WAIT0()  asm volatile("cp.async.wait_group 0;" ::: "memory")

// ======================= gate+up GEMM with fused SwiGLU ========================
template<bool GROUPED, bool TOKMAP>
__global__ void __launch_bounds__(256, 2)
gemmh_act_kernel(const fp16* __restrict__ Ah, int lda,
                 const fp16* __restrict__ Bg, const fp16* __restrict__ Bu,
                 size_t b_estride,
                 int KD, fp16* __restrict__ Hout, int ldh)
{
    int e = blockIdx.z;
    int rbeg, rend;
    if (GROUPED) { rbeg = g_off[e]; rend = g_off[e + 1]; }
    else         { rbeg = 0;        rend = T_TOK; }
    int row0 = rbeg + blockIdx.y * 128;
    if (row0 >= rend) return;
    int n0h = blockIdx.x * 64;

    const fp16* Bge = Bg + (size_t)e * b_estride;
    const fp16* Bue = Bu + (size_t)e * b_estride;

    extern __shared__ __align__(16) char dynsmem[];
    uint32_t sbase = smem_u32(dynsmem);

    int tid  = threadIdx.x;
    int lane = tid & 31, wid = tid >> 5;
    int wm = (wid >> 2) * 64;
    int wn = (wid & 3) * 32;

    int srow = tid >> 1;
    int kh16 = (tid & 1) << 4;
    int  arow_s = row0 + srow;
    bool avalid = (arow_s < rend);
    const fp16* pAh = Ah;
    if (avalid) {
        int tokr = TOKMAP ? g_ptok[arow_s] : arow_s;
        pAh = Ah + (size_t)tokr * lda + kh16;
    }
    const fp16* pBh = (srow < 64)
        ? Bge + (size_t)(n0h + srow) * KD + kh16
        : Bue + (size_t)(n0h + srow - 64) * KD + kh16;
    uint32_t st_off = (uint32_t)(srow * ROWB + (tid & 1) * 32);
    uint32_t asz = avalid ? 16u : 0u;

    int a_r  = wm + (lane & 7) + ((lane >> 3) & 1) * 8;
    int a_k  = ((lane >> 4) & 1) * 8;
    uint32_t a_lm = (uint32_t)(a_r * ROWB + a_k * 2);
    int b_r  = wn + (lane & 7) + ((lane >> 4) & 1) * 8;
    int b_k  = ((lane >> 3) & 1) * 8;
    uint32_t b_lm = (uint32_t)(b_r * ROWB + b_k * 2);

    float acc[4][4][4];
    #pragma unroll
    for (int i = 0; i < 4; i++)
        #pragma unroll
        for (int j = 0; j < 4; j++)
            #pragma unroll
            for (int q = 0; q < 4; q++) acc[i][j][q] = 0.f;

    int nchunk = KD >> 5;

    auto issue = [&](int ch) {
        if (ch < nchunk) {
            uint32_t sb = sbase + (uint32_t)(ch % NSTG) * STG_B;
            int k0 = ch << 5;
            const fp16* sa_h = pAh + k0;
            const fp16* sb_h = pBh + k0;
            CP16(sb + AH_OFF + st_off,      sa_h,     asz);
            CP16(sb + AH_OFF + st_off + 16, sa_h + 8, asz);
            CP16(sb + BH_OFF + st_off,      sb_h,     16u);
            CP16(sb + BH_OFF + st_off + 16, sb_h + 8, 16u);
        }
        CP_COMMIT();
    };

    issue(0);
    issue(1);
    issue(2);

    for (int ch = 0; ch < nchunk; ch++) {
        CP_WAIT2();
        __syncthreads();

        uint32_t sb = sbase + (uint32_t)(ch % NSTG) * STG_B;
        #pragma unroll
        for (int ks = 0; ks < 2; ks++) {
            uint32_t kso = (uint32_t)(ks * 32);
            uint32_t ah[4][4], bh[4][2];
            #pragma unroll
            for (int mt = 0; mt < 4; mt++) {
                uint32_t ad = sb + a_lm + (uint32_t)(mt * 16 * ROWB) + kso;
                LDSM_X4(ah[mt][0], ah[mt][1], ah[mt][2], ah[mt][3], ad + AH_OFF);
            }
            #pragma unroll
            for (int nt2 = 0; nt2 < 2; nt2++) {
                uint32_t bd = sb + b_lm + (uint32_t)(nt2 * 16 * ROWB) + kso;
                uint32_t r0, r1, r2, r3;
                LDSM_X4(r0, r1, r2, r3, bd + BH_OFF);
                bh[2 * nt2][0] = r0; bh[2 * nt2][1] = r1;
                bh[2 * nt2 + 1][0] = r2; bh[2 * nt2 + 1][1] = r3;
            }
            #pragma unroll
            for (int mt = 0; mt < 4; mt++)
                #pragma unroll
                for (int nt = 0; nt < 4; nt++)
                    MMA16816F16(acc[mt][nt], ah[mt], bh[nt]);
        }

        if (ch + 1 < nchunk) issue(ch + 3);
    }

    // ---- fused SwiGLU epilogue via smem staging --------------------------------
    CP_WAIT0();
    __syncthreads();

    float* eps = (float*)dynsmem;
    int gr = lane >> 2, t4 = lane & 3;
    #pragma unroll
    for (int mt = 0; mt < 4; mt++) {
        int L0 = wm + mt * 16 + gr;
        int L1 = L0 + 8;
        #pragma unroll
        for (int nt = 0; nt < 4; nt++) {
            int C = wn + nt * 8 + t4 * 2;
            *(float2*)(eps + L0 * EP_LD + C) = make_float2(acc[mt][nt][0], acc[mt][nt][1]);
            *(float2*)(eps + L1 * EP_LD + C) = make_float2(acc[mt][nt][2], acc[mt][nt][3]);
        }
    }
    __syncthreads();

    {
        int r  = tid >> 1;
        int cb = (tid & 1) * 32;
        int R  = row0 + r;
        if (R < rend) {
            fp16* ho = Hout + (size_t)R * ldh + n0h + cb;
            #pragma unroll
            for (int i = 0; i < 8; i++) {
                float4 gv = *(float4*)(eps + r * EP_LD + cb + 4 * i);
                float4 uv = *(float4*)(eps + r * EP_LD + 64 + cb + 4 * i);
                float h0 = gv.x * uv.x / (1.f + expf(-gv.x));
                float h1 = gv.y * uv.y / (1.f + expf(-gv.y));
                float h2 = gv.z * uv.z / (1.f + expf(-gv.z));
                float h3 = gv.w * uv.w / (1.f + expf(-gv.w));
                __half2 p0 = __floats2half2_rn(h0, h1);
                __half2 p1 = __floats2half2_rn(h2, h3);
                *(uint2*)(ho + 4 * i) = make_uint2(*(uint32_t*)&p0, *(uint32_t*)&p1);
            }
        }
    }
}

// ======================= down GEMM =============================================
// HOUT: store weighted result as fp16 (routed); else fp32 store (shared).
template<bool GROUPED, bool TOKMAP, bool WEIGHT, bool HOUT>
__global__ void __launch_bounds__(256, 2)
gemmh_kernel(const fp16* __restrict__ Ah, int lda,
             const fp16* __restrict__ B0h, size_t b_estride,
             int KD, void* __restrict__ CoutV, int ldc)
{
    int e = blockIdx.z;
    int rbeg, rend;
    if (GROUPED) { rbeg = g_off[e]; rend = g_off[e + 1]; }
    else         { rbeg = 0;        rend = T_TOK; }
    int row0 = rbeg + blockIdx.y * 128;
    if (row0 >= rend) return;
    int n0 = blockIdx.x * 128;

    const fp16* Bh = B0h + (size_t)e * b_estride;
    int brow0 = n0;

    extern __shared__ __align__(16) char dynsmem[];
    uint32_t sbase = smem_u32(dynsmem);

    int tid  = threadIdx.x;
    int lane = tid & 31, wid = tid >> 5;
    int wm = (wid >> 2) * 64;
    int wn = (wid & 3) * 32;

    int srow = tid >> 1;
    int kh16 = (tid & 1) << 4;
    int  arow_s = row0 + srow;
    bool avalid = (arow_s < rend);
    const fp16* pAh = Ah;
    if (avalid) {
        int tokr = TOKMAP ? g_ptok[arow_s] : arow_s;
        pAh = Ah + (size_t)tokr * lda + kh16;
    }
    const fp16* pBh = Bh + (size_t)(brow0 + srow) * KD + kh16;
    uint32_t st_off = (uint32_t)(srow * ROWB + (tid & 1) * 32);
    uint32_t asz = avalid ? 16u : 0u;

    int a_r  = wm + (lane & 7) + ((lane >> 3) & 1) * 8;
    int a_k  = ((lane >> 4) & 1) * 8;
    uint32_t a_lm = (uint32_t)(a_r * ROWB + a_k * 2);
    int b_r  = wn + (lane & 7) + ((lane >> 4) & 1) * 8;
    int b_k  = ((lane >> 3) & 1) * 8;
    uint32_t b_lm = (uint32_t)(b_r * ROWB + b_k * 2);

    float acc[4][4][4];
    #pragma unroll
    for (int i = 0; i < 4; i++)
        #pragma unroll
        for (int j = 0; j < 4; j++)
            #pragma unroll
            for (int q = 0; q < 4; q++) acc[i][j][q] = 0.f;

    int nchunk = KD >> 5;

    auto issue = [&](int ch) {
        if (ch < nchunk) {
            uint32_t sb = sbase + (uint32_t)(ch % NSTG) * STG_B;
            int k0 = ch << 5;
            const fp16* sa_h = pAh + k0;
            const fp16* sb_h = pBh + k0;
            CP16(sb + AH_OFF + st_off,      sa_h,     asz);
            CP16(sb + AH_OFF + st_off + 16, sa_h + 8, asz);
            CP16(sb + BH_OFF + st_off,      sb_h,     16u);
            CP16(sb + BH_OFF + st_off + 16, sb_h + 8, 16u);
        }
        CP_COMMIT();
    };

    issue(0);
    issue(1);
    issue(2);

    for (int ch = 0; ch < nchunk; ch++) {
        CP_WAIT2();
        __syncthreads();

        uint32_t sb = sbase + (uint32_t)(ch % NSTG) * STG_B;
        #pragma unroll
        for (int ks = 0; ks < 2; ks++) {
            uint32_t kso = (uint32_t)(ks * 32);
            uint32_t ah[4][4], bh[4][2];
            #pragma unroll
            for (int mt = 0; mt < 4; mt++) {
                uint32_t ad = sb + a_lm + (uint32_t)(mt * 16 * ROWB) + kso;
                LDSM_X4(ah[mt][0], ah[mt][1], ah[mt][2], ah[mt][3], ad + AH_OFF);
            }
            #pragma unroll
            for (int nt2 = 0; nt2 < 2; nt2++) {
                uint32_t bd = sb + b_lm + (uint32_t)(nt2 * 16 * ROWB) + kso;
                uint32_t r0, r1, r2, r3;
                LDSM_X4(r0, r1, r2, r3, bd + BH_OFF);
                bh[2 * nt2][0] = r0; bh[2 * nt2][1] = r1;
                bh[2 * nt2 + 1][0] = r2; bh[2 * nt2 + 1][1] = r3;
            }
            #pragma unroll
            for (int mt = 0; mt < 4; mt++)
                #pragma unroll
                for (int nt = 0; nt < 4; nt++)
                    MMA16816F16(acc[mt][nt], ah[mt], bh[nt]);
        }

        if (ch + 1 < nchunk) issue(ch + 3);
    }

    // epilogue
    int g = lane >> 2, t4 = lane & 3;
    #pragma unroll
    for (int mt = 0; mt < 4; mt++) {
        int R0 = row0 + wm + mt * 16 + g;
        int R1 = R0 + 8;
        bool v0 = (R0 < rend), v1 = (R1 < rend);
        float w0 = 1.f, w1 = 1.f;
        if (WEIGHT) { if (v0) w0 = g_pw[R0]; if (v1) w1 = g_pw[R1]; }
        #pragma unroll
        for (int nt = 0; nt < 4; nt++) {
            int C = n0 + wn + nt * 8 + t4 * 2;
            if (HOUT) {
                fp16* Ch = (fp16*)CoutV;
                if (v0) {
                    __half2 p = __floats2half2_rn(acc[mt][nt][0] * w0, acc[mt][nt][1] * w0);
                    *(uint32_t*)(Ch + (size_t)R0 * ldc + C) = *(uint32_t*)&p;
                }
                if (v1) {
                    __half2 p = __floats2half2_rn(acc[mt][nt][2] * w1, acc[mt][nt][3] * w1);
                    *(uint32_t*)(Ch + (size_t)R1 * ldc + C) = *(uint32_t*)&p;
                }
            } else {
                float* Cf = (float*)CoutV;
                if (v0) {
                    float2 o = make_float2(acc[mt][nt][0] * w0, acc[mt][nt][1] * w0);
                    *(float2*)(Cf + (size_t)R0 * ldc + C) = o;
                }
                if (v1) {
                    float2 o = make_float2(acc[mt][nt][2] * w1, acc[mt][nt][3] * w1);
                    *(float2*)(Cf + (size_t)R1 * ldc + C) = o;
                }
            }
        }
    }
}

// ======================= combine ===============================================
__global__ void combine_kernel(float* __restrict__ out) {
    int idx = blockIdx.x * blockDim.x + threadIdx.x;
    int t = idx >> 8;
    int c = (idx & 255) << 2;
    float4 acc = *(const float4*)(g_ysh + (size_t)t * 1024 + c);
    #pragma unroll
    for (int r = 0; r < TOPK; r++) {
        int p = g_pos[t * TOPK + r];
        uint2 hv = *(const uint2*)(g_yh + (size_t)p * 1024 + c);
        __half2 a = *(__half2*)&hv.x;
        __half2 b = *(__half2*)&hv.y;
        float2 fa = __half22float2(a);
        float2 fb = __half22float2(b);
        acc.x += fa.x; acc.y += fa.y; acc.z += fb.x; acc.w += fb.y;
    }
    *(float4*)(out + (size_t)t * 1024 + c) = acc;
}

// ======================= launch ================================================
extern "C" void kernel_launch(void* const* d_in, const int* in_sizes, int n_in,
                              void* d_out, int out_size) {
    const float* x   = (const float*)d_in[0];
    const float* rw  = (const float*)d_in[1];
    const float* eb  = (const float*)d_in[2];
    const float* gw  = (const float*)d_in[3];
    const float* uw  = (const float*)d_in[4];
    const float* dw  = (const float*)d_in[5];
    const float* shg = (const float*)d_in[6];
    const float* shu = (const float*)d_in[7];
    const float* shd = (const float*)d_in[8];
    float* out = (float*)d_out;

    cudaFuncSetAttribute(gemmh_act_kernel<false, false>,
                         cudaFuncAttributeMaxDynamicSharedMemorySize, SMEM_DYN);
    cudaFuncSetAttribute(gemmh_act_kernel<true, true>,
                         cudaFuncAttributeMaxDynamicSharedMemorySize, SMEM_DYN);
    cudaFuncSetAttribute(gemmh_kernel<false, false, false, false>,
                         cudaFuncAttributeMaxDynamicSharedMemorySize, SMEM_DYN);
    cudaFuncSetAttribute(gemmh_kernel<true, false, true, true>,
                         cudaFuncAttributeMaxDynamicSharedMemorySize, SMEM_DYN);

    float *gys;
    fp16 *yh, *xh, *gwh, *uwh, *dwh, *sgh, *suh, *sdh, *hh, *hsh;
    cudaGetSymbolAddress((void**)&yh,   g_yh);
    cudaGetSymbolAddress((void**)&gys,  g_ysh);
    cudaGetSymbolAddress((void**)&xh,  g_xh);
    cudaGetSymbolAddress((void**)&gwh, g_gwh);
    cudaGetSymbolAddress((void**)&uwh, g_uwh);
    cudaGetSymbolAddress((void**)&dwh, g_dwh);
    cudaGetSymbolAddress((void**)&sgh, g_sgh);
    cudaGetSymbolAddress((void**)&suh, g_suh);
    cudaGetSymbolAddress((void**)&sdh, g_sdh);
    cudaGetSymbolAddress((void**)&hh,  g_hh);
    cudaGetSymbolAddress((void**)&hsh, g_hsh);

    // ---- fused convert of all operands (+ routing counter init) ----
    CvtArgs ca;
    const float* srcs[NSEG] = {x, gw, uw, dw, shg, shu, shd};
    fp16*        dsts[NSEG] = {xh, gwh, uwh, dwh, sgh, suh, sdh};
    const int    n4s [NSEG] = {
        (T_TOK * HDIM) / 4,
        (NE * IMOE * HDIM) / 4, (NE * IMOE * HDIM) / 4, (NE * HDIM * IMOE) / 4,
        (HDIM * 1024) / 4, (HDIM * 1024) / 4, (HDIM * 1024) / 4
    };
    int cum = 0;
    for (int s = 0; s < NSEG; s++) {
        ca.src[s] = (const float4*)srcs[s];
        ca.dst[s] = (uint2*)dsts[s];
        ca.cum[s] = cum;
        cum += n4s[s];
    }
    cvt_all_kernel<<<(cum + 255) / 256, 256>>>(ca, cum);

    // ---- routing ----
    router_kernel<<<T_TOK, NE * 32>>>(x, rw, eb);
    scan_kernel<<<1, 32>>>();
    scatter_kernel<<<(T_TOK * TOPK + 255) / 256, 256>>>();

    // ---- shared expert: fused gate+up+act, then down (fp32 out) ----
    gemmh_act_kernel<false, false><<<dim3(16, 16, 1), 256, SMEM_DYN>>>(
        xh, HDIM, sgh, suh, 0, 1024, hsh, 1024);
    gemmh_kernel<false, false, false, false><<<dim3(8, 16, 1), 256, SMEM_DYN>>>(
        hsh, 1024, sdh, 0, 1024, gys, 1024);

    // ---- routed experts: fused gate+up+act, then down (weighted fp16 out) ----
    gemmh_act_kernel<true, true><<<dim3(8, 16, NE), 256, SMEM_DYN>>>(
        xh, HDIM, gwh, uwh, (size_t)IMOE * HDIM, 1024, hh, 512);
    gemmh_kernel<true, false, true, true><<<dim3(8, 16, NE), 256, SMEM_DYN>>>(
        hh, 512, dwh, (size_t)HDIM * IMOE, 512, yh, 1024);

    // ---- combine ----
    combine_kernel<<<(T_TOK * 1024 / 4) / 256, 256>>>(out);
}

// round 14
// speedup vs baseline: 4.5899x; 1.0029x over previous
#include <cuda_runtime.h>
#include <cuda_fp16.h>
#include <math.h>
#include <stdint.h>

#define T_TOK 2048
#define HDIM  1024
#define NE    16
#define TOPK  4
#define NG    4
#define TGSEL 2
#define IMOE  512
#define RSCALE 2.5f

typedef __half fp16;

// ======================= device scratch ========================================
__device__ int   g_tidx[T_TOK * TOPK];
__device__ float g_tw  [T_TOK * TOPK];
__device__ int   g_cur [NE];
__device__ int   g_off [NE + 1];
__device__ int   g_ptok[T_TOK * TOPK];
__device__ int   g_pos [T_TOK * TOPK];
__device__ float g_pw  [T_TOK * TOPK];

__device__ fp16  g_yh [(size_t)T_TOK * TOPK * 1024];   // routed down out (weighted, fp16)
__device__ float g_ysh[(size_t)T_TOK * 1024];           // shared down out (fp32)

// fp16 operands
__device__ fp16 g_xh [T_TOK * HDIM];
__device__ fp16 g_hh [T_TOK * TOPK * IMOE];
__device__ fp16 g_hsh[T_TOK * 1024];
__device__ fp16 g_gwh[NE * IMOE * HDIM];
__device__ fp16 g_uwh[NE * IMOE * HDIM];
__device__ fp16 g_dwh[NE * HDIM * IMOE];
__device__ fp16 g_sgh[HDIM * 1024];
__device__ fp16 g_suh[HDIM * 1024];
__device__ fp16 g_sdh[HDIM * 1024];

// ======================= fused prep: convert + router ==========================
#define NSEG 7
#define CVT_TOTAL 7602176            // total float4 units across all 7 segments
#define CVT_BLKS  (CVT_TOTAL / 512)  // 14848 (exact)

struct CvtArgs {
    const float4* src[NSEG];
    uint2*        dst[NSEG];
    int           cum[NSEG];
};

__global__ void __launch_bounds__(512)
prep_kernel(CvtArgs a,
            const float* __restrict__ x,
            const float* __restrict__ rw,
            const float* __restrict__ ebias) {
    if (blockIdx.x < CVT_BLKS) {
        // ---- convert part ----
        int i = blockIdx.x * 512 + threadIdx.x;
        if (i < CVT_TOTAL) {
            int s = 0;
            #pragma unroll
            for (int k = 1; k < NSEG; k++) if (i >= a.cum[k]) s = k;
            int off = i - a.cum[s];
            float4 v = a.src[s][off];
            __half2 p0 = __floats2half2_rn(v.x, v.y);
            __half2 p1 = __floats2half2_rn(v.z, v.w);
            a.dst[s][off] = make_uint2(*(uint32_t*)&p0, *(uint32_t*)&p1);
        }
        return;
    }

    // ---- router part (one block per token, 16 warps) ----
    int t    = blockIdx.x - CVT_BLKS;
    int w    = threadIdx.x >> 5;
    int lane = threadIdx.x & 31;

    const float* xr = x  + (size_t)t * HDIM;
    const float* wr = rw + (size_t)w * HDIM;
    float s = 0.f;
    for (int k = lane; k < HDIM; k += 32) s += xr[k] * wr[k];
    #pragma unroll
    for (int o = 16; o; o >>= 1) s += __shfl_xor_sync(0xffffffffu, s, o);

    __shared__ float sdot[NE];
    if (lane == 0) sdot[w] = s;
    __syncthreads();

    if (threadIdx.x == 0) {
        float sraw[NE], sc[NE];
        #pragma unroll
        for (int e = 0; e < NE; e++) {
            sraw[e] = 1.f / (1.f + expf(-sdot[e]));
            sc[e]   = sraw[e] + ebias[e];
        }
        float gsc[NG];
        #pragma unroll
        for (int g = 0; g < NG; g++) {
            float m1 = -1e30f, m2 = -1e30f;
            #pragma unroll
            for (int j = 0; j < NE / NG; j++) {
                float v = sc[g * (NE / NG) + j];
                if (v > m1) { m2 = m1; m1 = v; }
                else if (v > m2) { m2 = v; }
            }
            gsc[g] = m1 + m2;
        }
        bool gsel[NG] = {false, false, false, false};
        for (int r = 0; r < TGSEL; r++) {
            int best = -1; float bv = -1e30f;
            for (int g = 0; g < NG; g++)
                if (!gsel[g] && gsc[g] > bv) { bv = gsc[g]; best = g; }
            gsel[best] = true;
        }
        float masked[NE];
        #pragma unroll
        for (int e = 0; e < NE; e++)
            masked[e] = gsel[e / (NE / NG)] ? sc[e] : 0.0f;
        int idx[TOPK]; float tw[TOPK]; float wsum = 0.f;
        for (int r = 0; r < TOPK; r++) {
            int best = 0; float bv = -1e30f;
            for (int e = 0; e < NE; e++)
                if (masked[e] > bv) { bv = masked[e]; best = e; }
            idx[r] = best; tw[r] = sraw[best];
            masked[best] = -1e30f;
            wsum += tw[r];
        }
        float inv = RSCALE / (wsum + 1e-20f);
        for (int r = 0; r < TOPK; r++) {
            g_tidx[t * TOPK + r] = idx[r];
            g_tw  [t * TOPK + r] = tw[r] * inv;
        }
    }
}

// ======================= scan (histogram + prefix) =============================
__global__ void __launch_bounds__(512)
scan_kernel() {
    __shared__ int cnt[NE];
    int tid = threadIdx.x;
    if (tid < NE) cnt[tid] = 0;
    __syncthreads();
    for (int i = tid; i < T_TOK * TOPK; i += 512)
        atomicAdd(&cnt[g_tidx[i]], 1);
    __syncthreads();
    if (tid == 0) {
        int acc = 0;
        for (int e = 0; e < NE; e++) { g_off[e] = acc; acc += cnt[e]; }
        g_off[NE] = acc;
    }
    if (tid < NE) g_cur[tid] = 0;
}

__global__ void scatter_kernel() {
    int s = blockIdx.x * blockDim.x + threadIdx.x;
    if (s >= T_TOK * TOPK) return;
    int e   = g_tidx[s];
    int pos = g_off[e] + atomicAdd(&g_cur[e], 1);
    g_ptok[pos] = s >> 2;
    g_pw  [pos] = g_tw[s];
    g_pos [s]   = pos;
}

// ======================= shared GEMM machinery =================================
#define ROWB   80
#define AH_OFF 0
#define BH_OFF 10240
#define STG_B  20480
#define NSTG   4
#define SMEM_DYN (NSTG * STG_B)
#define EP_LD  132

static __device__ __forceinline__ uint32_t smem_u32(const void* p) {
    uint32_t a;
    asm("{ .reg .u64 t; cvta.to.shared.u64 t, %1; cvt.u32.u64 %0, t; }"
        : "=r"(a) : "l"(p));
    return a;
}

#define LDSM_X4(r0, r1, r2, r3, addr) \
    asm volatile("ldmatrix.sync.aligned.m8n8.x4.shared.b16 {%0,%1,%2,%3}, [%4];" \
        : "=r"(r0), "=r"(r1), "=r"(r2), "=r"(r3) : "r"(addr))

#define MMA16816F16(d, a, b) \
    asm volatile("mma.sync.aligned.m16n8k16.row.col.f32.f16.f16.f32 " \
        "{%0,%1,%2,%3},{%4,%5,%6,%7},{%8,%9},{%0,%1,%2,%3};" \
        : "+f"((d)[0]), "+f"((d)[1]), "+f"((d)[2]), "+f"((d)[3]) \
        : "r"((a)[0]), "r"((a)[1]), "r"((a)[2]), "r"((a)[3]), \
          "r"((b)[0]), "r"((b)[1]))

#define CP16(dst, src, sz) \
    asm volatile("cp.async.cg.shared.global [%0], [%1], 16, %2;" \
        :: "r"(dst), "l"(src), "r"(sz) : "memory")
#define CP_COMMIT() asm volatile("cp.async.commit_group;" ::: "memory")
#define CP_WAIT2()  asm volatile("cp.async.wait_group 2;" ::: "memory")
#define CP_WAIT0()  asm volatile("cp.async.wait_group 0;" ::: "memory")

// ======================= gateup_all: routed (z<NE) + shared (z==NE) ============
// B tile rows 0-63 = gate, 64-127 = up for the same 64 channels; fused SwiGLU
// epilogue writes fp16 h directly. Mainloop K=1024 for both variants.
__global__ void __launch_bounds__(256, 2)
gateup_all_kernel(const fp16* __restrict__ xh,
                  const fp16* __restrict__ gwh, const fp16* __restrict__ uwh,
                  const fp16* __restrict__ sgh, const fp16* __restrict__ suh,
                  fp16* __restrict__ hh, fp16* __restrict__ hsh)
{
    int z = blockIdx.z;
    bool se = (z == NE);
    int rbeg, rend, nxb, ldh;
    const fp16 *Bg, *Bu;
    fp16* Hout;
    if (se) {
        rbeg = 0; rend = T_TOK; nxb = 16; ldh = 1024;
        Bg = sgh; Bu = suh; Hout = hsh;
    } else {
        rbeg = g_off[z]; rend = g_off[z + 1]; nxb = 8; ldh = 512;
        Bg = gwh + (size_t)z * IMOE * HDIM;
        Bu = uwh + (size_t)z * IMOE * HDIM;
        Hout = hh;
    }
    if (blockIdx.x >= nxb) return;
    int row0 = rbeg + blockIdx.y * 128;
    if (row0 >= rend) return;
    int n0h = blockIdx.x * 64;
    const int KD = 1024;

    extern __shared__ __align__(16) char dynsmem[];
    uint32_t sbase = smem_u32(dynsmem);

    int tid  = threadIdx.x;
    int lane = tid & 31, wid = tid >> 5;
    int wm = (wid >> 2) * 64;
    int wn = (wid & 3) * 32;

    int srow = tid >> 1;
    int kh16 = (tid & 1) << 4;
    int  arow_s = row0 + srow;
    bool avalid = (arow_s < rend);
    const fp16* pAh = xh;
    if (avalid) {
        int tokr = se ? arow_s : g_ptok[arow_s];
        pAh = xh + (size_t)tokr * HDIM + kh16;
    }
    const fp16* pBh = (srow < 64)
        ? Bg + (size_t)(n0h + srow) * KD + kh16
        : Bu + (size_t)(n0h + srow - 64) * KD + kh16;
    uint32_t st_off = (uint32_t)(srow * ROWB + (tid & 1) * 32);
    uint32_t asz = avalid ? 16u : 0u;

    int a_r  = wm + (lane & 7) + ((lane >> 3) & 1) * 8;
    int a_k  = ((lane >> 4) & 1) * 8;
    uint32_t a_lm = (uint32_t)(a_r * ROWB + a_k * 2);
    int b_r  = wn + (lane & 7) + ((lane >> 4) & 1) * 8;
    int b_k  = ((lane >> 3) & 1) * 8;
    uint32_t b_lm = (uint32_t)(b_r * ROWB + b_k * 2);

    float acc[4][4][4];
    #pragma unroll
    for (int i = 0; i < 4; i++)
        #pragma unroll
        for (int j = 0; j < 4; j++)
            #pragma unroll
            for (int q = 0; q < 4; q++) acc[i][j][q] = 0.f;

    const int nchunk = KD >> 5;

    auto issue = [&](int ch) {
        if (ch < nchunk) {
            uint32_t sb = sbase + (uint32_t)(ch % NSTG) * STG_B;
            int k0 = ch << 5;
            const fp16* sa_h = pAh + k0;
            const fp16* sb_h = pBh + k0;
            CP16(sb + AH_OFF + st_off,      sa_h,     asz);
            CP16(sb + AH_OFF + st_off + 16, sa_h + 8, asz);
            CP16(sb + BH_OFF + st_off,      sb_h,     16u);
            CP16(sb + BH_OFF + st_off + 16, sb_h + 8, 16u);
        }
        CP_COMMIT();
    };

    issue(0);
    issue(1);
    issue(2);

    for (int ch = 0; ch < nchunk; ch++) {
        CP_WAIT2();
        __syncthreads();

        uint32_t sb = sbase + (uint32_t)(ch % NSTG) * STG_B;
        #pragma unroll
        for (int ks = 0; ks < 2; ks++) {
            uint32_t kso = (uint32_t)(ks * 32);
            uint32_t ah[4][4], bh[4][2];
            #pragma unroll
            for (int mt = 0; mt < 4; mt++) {
                uint32_t ad = sb + a_lm + (uint32_t)(mt * 16 * ROWB) + kso;
                LDSM_X4(ah[mt][0], ah[mt][1], ah[mt][2], ah[mt][3], ad + AH_OFF);
            }
            #pragma unroll
            for (int nt2 = 0; nt2 < 2; nt2++) {
                uint32_t bd = sb + b_lm + (uint32_t)(nt2 * 16 * ROWB) + kso;
                uint32_t r0, r1, r2, r3;
                LDSM_X4(r0, r1, r2, r3, bd + BH_OFF);
                bh[2 * nt2][0] = r0; bh[2 * nt2][1] = r1;
                bh[2 * nt2 + 1][0] = r2; bh[2 * nt2 + 1][1] = r3;
            }
            #pragma unroll
            for (int mt = 0; mt < 4; mt++)
                #pragma unroll
                for (int nt = 0; nt < 4; nt++)
                    MMA16816F16(acc[mt][nt], ah[mt], bh[nt]);
        }

        if (ch + 1 < nchunk) issue(ch + 3);
    }

    // fused SwiGLU epilogue
    CP_WAIT0();
    __syncthreads();

    float* eps = (float*)dynsmem;
    int gr = lane >> 2, t4 = lane & 3;
    #pragma unroll
    for (int mt = 0; mt < 4; mt++) {
        int L0 = wm + mt * 16 + gr;
        int L1 = L0 + 8;
        #pragma unroll
        for (int nt = 0; nt < 4; nt++) {
            int C = wn + nt * 8 + t4 * 2;
            *(float2*)(eps + L0 * EP_LD + C) = make_float2(acc[mt][nt][0], acc[mt][nt][1]);
            *(float2*)(eps + L1 * EP_LD + C) = make_float2(acc[mt][nt][2], acc[mt][nt][3]);
        }
    }
    __syncthreads();

    {
        int r  = tid >> 1;
        int cb = (tid & 1) * 32;
        int R  = row0 + r;
        if (R < rend) {
            fp16* ho = Hout + (size_t)R * ldh + n0h + cb;
            #pragma unroll
            for (int i = 0; i < 8; i++) {
                float4 gv = *(float4*)(eps + r * EP_LD + cb + 4 * i);
                float4 uv = *(float4*)(eps + r * EP_LD + 64 + cb + 4 * i);
                float h0 = gv.x * uv.x / (1.f + expf(-gv.x));
                float h1 = gv.y * uv.y / (1.f + expf(-gv.y));
                float h2 = gv.z * uv.z / (1.f + expf(-gv.z));
                float h3 = gv.w * uv.w / (1.f + expf(-gv.w));
                __half2 p0 = __floats2half2_rn(h0, h1);
                __half2 p1 = __floats2half2_rn(h2, h3);
                *(uint2*)(ho + 4 * i) = make_uint2(*(uint32_t*)&p0, *(uint32_t*)&p1);
            }
        }
    }
}

// ======================= down_all: routed (z<NE) + shared (z==NE) ==============
__global__ void __launch_bounds__(256, 2)
down_all_kernel(const fp16* __restrict__ hh, const fp16* __restrict__ hsh,
                const fp16* __restrict__ dwh, const fp16* __restrict__ sdh,
                fp16* __restrict__ yh, float* __restrict__ ysh)
{
    int z = blockIdx.z;
    bool se = (z == NE);
    int rbeg, rend, lda, KD;
    const fp16 *Ah, *Bh;
    if (se) {
        rbeg = 0; rend = T_TOK; lda = 1024; KD = 1024;
        Ah = hsh; Bh = sdh;
    } else {
        rbeg = g_off[z]; rend = g_off[z + 1]; lda = 512; KD = 512;
        Ah = hh; Bh = dwh + (size_t)z * HDIM * IMOE;
    }
    int row0 = rbeg + blockIdx.y * 128;
    if (row0 >= rend) return;
    int n0 = blockIdx.x * 128;

    extern __shared__ __align__(16) char dynsmem[];
    uint32_t sbase = smem_u32(dynsmem);

    int tid  = threadIdx.x;
    int lane = tid & 31, wid = tid >> 5;
    int wm = (wid >> 2) * 64;
    int wn = (wid & 3) * 32;

    int srow = tid >> 1;
    int kh16 = (tid & 1) << 4;
    int  arow_s = row0 + srow;
    bool avalid = (arow_s < rend);
    const fp16* pAh = Ah;
    if (avalid) pAh = Ah + (size_t)arow_s * lda + kh16;
    const fp16* pBh = Bh + (size_t)(n0 + srow) * KD + kh16;
    uint32_t st_off = (uint32_t)(srow * ROWB + (tid & 1) * 32);
    uint32_t asz = avalid ? 16u : 0u;

    int a_r  = wm + (lane & 7) + ((lane >> 3) & 1) * 8;
    int a_k  = ((lane >> 4) & 1) * 8;
    uint32_t a_lm = (uint32_t)(a_r * ROWB + a_k * 2);
    int b_r  = wn + (lane & 7) + ((lane >> 4) & 1) * 8;
    int b_k  = ((lane >> 3) & 1) * 8;
    uint32_t b_lm = (uint32_t)(b_r * ROWB + b_k * 2);

    float acc[4][4][4];
    #pragma unroll
    for (int i = 0; i < 4; i++)
        #pragma unroll
        for (int j = 0; j < 4; j++)
            #pragma unroll
            for (int q = 0; q < 4; q++) acc[i][j][q] = 0.f;

    int nchunk = KD >> 5;

    auto issue = [&](int ch) {
        if (ch < nchunk) {
            uint32_t sb = sbase + (uint32_t)(ch % NSTG) * STG_B;
            int k0 = ch << 5;
            const fp16* sa_h = pAh + k0;
            const fp16* sb_h = pBh + k0;
            CP16(sb + AH_OFF + st_off,      sa_h,     asz);
            CP16(sb + AH_OFF + st_off + 16, sa_h + 8, asz);
            CP16(sb + BH_OFF + st_off,      sb_h,     16u);
            CP16(sb + BH_OFF + st_off + 16, sb_h + 8, 16u);
        }
        CP_COMMIT();
    };

    issue(0);
    issue(1);
    issue(2);

    for (int ch = 0; ch < nchunk; ch++) {
        CP_WAIT2();
        __syncthreads();

        uint32_t sb = sbase + (uint32_t)(ch % NSTG) * STG_B;
        #pragma unroll
        for (int ks = 0; ks < 2; ks++) {
            uint32_t kso = (uint32_t)(ks * 32);
            uint32_t ah[4][4], bh[4][2];
            #pragma unroll
            for (int mt = 0; mt < 4; mt++) {
                uint32_t ad = sb + a_lm + (uint32_t)(mt * 16 * ROWB) + kso;
                LDSM_X4(ah[mt][0], ah[mt][1], ah[mt][2], ah[mt][3], ad + AH_OFF);
            }
            #pragma unroll
            for (int nt2 = 0; nt2 < 2; nt2++) {
                uint32_t bd = sb + b_lm + (uint32_t)(nt2 * 16 * ROWB) + kso;
                uint32_t r0, r1, r2, r3;
                LDSM_X4(r0, r1, r2, r3, bd + BH_OFF);
                bh[2 * nt2][0] = r0; bh[2 * nt2][1] = r1;
                bh[2 * nt2 + 1][0] = r2; bh[2 * nt2 + 1][1] = r3;
            }
            #pragma unroll
            for (int mt = 0; mt < 4; mt++)
                #pragma unroll
                for (int nt = 0; nt < 4; nt++)
                    MMA16816F16(acc[mt][nt], ah[mt], bh[nt]);
        }

        if (ch + 1 < nchunk) issue(ch + 3);
    }

    // epilogue
    int g = lane >> 2, t4 = lane & 3;
    #pragma unroll
    for (int mt = 0; mt < 4; mt++) {
        int R0 = row0 + wm + mt * 16 + g;
        int R1 = R0 + 8;
        bool v0 = (R0 < rend), v1 = (R1 < rend);
        #pragma unroll
        for (int nt = 0; nt < 4; nt++) {
            int C = n0 + wn + nt * 8 + t4 * 2;
            if (se) {
                if (v0) *(float2*)(ysh + (size_t)R0 * 1024 + C) =
                    make_float2(acc[mt][nt][0], acc[mt][nt][1]);
                if (v1) *(float2*)(ysh + (size_t)R1 * 1024 + C) =
                    make_float2(acc[mt][nt][2], acc[mt][nt][3]);
            } else {
                if (v0) {
                    float w0 = g_pw[R0];
                    __half2 p = __floats2half2_rn(acc[mt][nt][0] * w0, acc[mt][nt][1] * w0);
                    *(uint32_t*)(yh + (size_t)R0 * 1024 + C) = *(uint32_t*)&p;
                }
                if (v1) {
                    float w1 = g_pw[R1];
                    __half2 p = __floats2half2_rn(acc[mt][nt][2] * w1, acc[mt][nt][3] * w1);
                    *(uint32_t*)(yh + (size_t)R1 * 1024 + C) = *(uint32_t*)&p;
                }
            }
        }
    }
}

// ======================= combine ===============================================
__global__ void combine_kernel(float* __restrict__ out) {
    int idx = blockIdx.x * blockDim.x + threadIdx.x;
    int t = idx >> 8;
    int c = (idx & 255) << 2;
    float4 acc = *(const float4*)(g_ysh + (size_t)t * 1024 + c);
    #pragma unroll
    for (int r = 0; r < TOPK; r++) {
        int p = g_pos[t * TOPK + r];
        uint2 hv = *(const uint2*)(g_yh + (size_t)p * 1024 + c);
        __half2 a = *(__half2*)&hv.x;
        __half2 b = *(__half2*)&hv.y;
        float2 fa = __half22float2(a);
        float2 fb = __half22float2(b);
        acc.x += fa.x; acc.y += fa.y; acc.z += fb.x; acc.w += fb.y;
    }
    *(float4*)(out + (size_t)t * 1024 + c) = acc;
}

// ======================= launch ================================================
extern "C" void kernel_launch(void* const* d_in, const int* in_sizes, int n_in,
                              void* d_out, int out_size) {
    const float* x   = (const float*)d_in[0];
    const float* rw  = (const float*)d_in[1];
    const float* eb  = (const float*)d_in[2];
    const float* gw  = (const float*)d_in[3];
    const float* uw  = (const float*)d_in[4];
    const float* dw  = (const float*)d_in[5];
    const float* shg = (const float*)d_in[6];
    const float* shu = (const float*)d_in[7];
    const float* shd = (const float*)d_in[8];
    float* out = (float*)d_out;

    cudaFuncSetAttribute(gateup_all_kernel,
                         cudaFuncAttributeMaxDynamicSharedMemorySize, SMEM_DYN);
    cudaFuncSetAttribute(down_all_kernel,
                         cudaFuncAttributeMaxDynamicSharedMemorySize, SMEM_DYN);

    float *gys;
    fp16 *yh, *xh, *gwh, *uwh, *dwh, *sgh, *suh, *sdh, *hh, *hsh;
    cudaGetSymbolAddress((void**)&yh,   g_yh);
    cudaGetSymbolAddress((void**)&gys,  g_ysh);
    cudaGetSymbolAddress((void**)&xh,  g_xh);
    cudaGetSymbolAddress((void**)&gwh, g_gwh);
    cudaGetSymbolAddress((void**)&uwh, g_uwh);
    cudaGetSymbolAddress((void**)&dwh, g_dwh);
    cudaGetSymbolAddress((void**)&sgh, g_sgh);
    cudaGetSymbolAddress((void**)&suh, g_suh);
    cudaGetSymbolAddress((void**)&sdh, g_sdh);
    cudaGetSymbolAddress((void**)&hh,  g_hh);
    cudaGetSymbolAddress((void**)&hsh, g_hsh);

    // ---- fused convert + router ----
    CvtArgs ca;
    const float* srcs[NSEG] = {x, gw, uw, dw, shg, shu, shd};
    fp16*        dsts[NSEG] = {xh, gwh, uwh, dwh, sgh, suh, sdh};
    const int    n4s [NSEG] = {
        (T_TOK * HDIM) / 4,
        (NE * IMOE * HDIM) / 4, (NE * IMOE * HDIM) / 4, (NE * HDIM * IMOE) / 4,
        (HDIM * 1024) / 4, (HDIM * 1024) / 4, (HDIM * 1024) / 4
    };
    int cum = 0;
    for (int s = 0; s < NSEG; s++) {
        ca.src[s] = (const float4*)srcs[s];
        ca.dst[s] = (uint2*)dsts[s];
        ca.cum[s] = cum;
        cum += n4s[s];
    }
    prep_kernel<<<CVT_BLKS + T_TOK, 512>>>(ca, x, rw, eb);
    scan_kernel<<<1, 512>>>();
    scatter_kernel<<<(T_TOK * TOPK + 255) / 256, 256>>>();

    // ---- merged gate+up (+SwiGLU) for routed + shared ----
    gateup_all_kernel<<<dim3(16, 16, NE + 1), 256, SMEM_DYN>>>(
        xh, gwh, uwh, sgh, suh, hh, hsh);

    // ---- merged down for routed + shared ----
    down_all_kernel<<<dim3(8, 16, NE + 1), 256, SMEM_DYN>>>(
        hh, hsh, dwh, sdh, yh, gys);

    // ---- combine ----
    combine_kernel<<<(T_TOK * 1024 / 4) / 256, 256>>>(out);
}